// round 1
// baseline (speedup 1.0000x reference)
#include <cuda_runtime.h>
#include <math.h>

// ---------------- problem dims ----------------
#define NB    8192          // batch / num agents
#define HD    128           // hidden
#define C1O   16
#define H1    18            // (40-5)/2+1
#define C2O   32
#define H2    8             // (18-3)/2+1
#define FLAT  2048          // 32*8*8
#define FEAT  144           // 128 + 16
#define G3H   384           // 3*H

// ---------------- scratch (device globals; no allocations allowed) ----------------
__device__ float g_conv1[NB * C1O * H1 * H1];   // ~170 MB
__device__ float g_flat [NB * FLAT];            // conv2 out, flattened (c,h,w)
__device__ float g_feat [NB * FEAT];            // [vis_feat | cls_emb]
__device__ float g_gi   [NB * G3H];
__device__ float g_gh   [NB * G3H];
__device__ float g_Q    [NB * HD];
__device__ float g_K    [NB * HD];
__device__ float g_V    [NB * HD];
__device__ float g_ctx  [NB * HD];
__device__ float g_swarm[NB * HD];
__device__ int   g_isI32;

// ---------------- class_ids dtype detection ----------------
// If the buffer is int64 (little-endian, values 0/1), every odd 32-bit word of the
// first 8192 words is zero. If int32, odd words are the actual 0/1 ids (some nonzero
// with overwhelming probability over 4096 samples).
__global__ void k_flag_init() { g_isI32 = 0; }
__global__ void k_flag_detect(const int* __restrict__ p) {
    int i = blockIdx.x * blockDim.x + threadIdx.x;   // i < 4096
    if (i < 4096 && p[2 * i + 1] != 0) g_isI32 = 1;
}

// ---------------- conv1: [N,3,40,40] -> relu -> [N,16,18,18], stride 2, 5x5 ----------------
__global__ void k_conv1(const float* __restrict__ img, const float* __restrict__ w,
                        const float* __restrict__ b, float* __restrict__ out) {
    __shared__ float ws[16 * 3 * 25];   // 1200
    for (int i = threadIdx.x; i < 1200; i += 256) ws[i] = w[i];
    __syncthreads();
    int idx = blockIdx.x * 256 + threadIdx.x;
    if (idx >= NB * C1O * H1 * H1) return;
    int ox = idx % H1;
    int oy = (idx / H1) % H1;
    int oc = (idx / (H1 * H1)) % C1O;
    int n  = idx / (C1O * H1 * H1);
    const float* ip = img + n * (3 * 40 * 40);
    const float* wp = ws + oc * 75;
    float s = b[oc];
    #pragma unroll
    for (int ic = 0; ic < 3; ic++) {
        const float* ipc = ip + ic * 1600 + oy * 80 + ox * 2;  // (2*oy)*40 + 2*ox
        #pragma unroll
        for (int ky = 0; ky < 5; ky++) {
            const float* row = ipc + ky * 40;
            const float* wr  = wp + ic * 25 + ky * 5;
            #pragma unroll
            for (int kx = 0; kx < 5; kx++) s += row[kx] * wr[kx];
        }
    }
    out[idx] = fmaxf(s, 0.f);
}

// ---------------- conv2: [N,16,18,18] -> relu -> flat [N,2048], stride 2, 3x3 ----------------
__global__ void k_conv2(const float* __restrict__ in, const float* __restrict__ w,
                        const float* __restrict__ b, float* __restrict__ out) {
    __shared__ float ws[32 * 16 * 9];   // 4608
    for (int i = threadIdx.x; i < 4608; i += 256) ws[i] = w[i];
    __syncthreads();
    int idx = blockIdx.x * 256 + threadIdx.x;   // idx == n*2048 + oc*64 + oy*8 + ox (flatten order)
    if (idx >= NB * FLAT) return;
    int ox = idx % H2;
    int oy = (idx / H2) % H2;
    int oc = (idx / (H2 * H2)) % C2O;
    int n  = idx / FLAT;
    const float* ip = in + n * (C1O * H1 * H1);
    const float* wp = ws + oc * 144;
    float s = b[oc];
    #pragma unroll 4
    for (int ic = 0; ic < 16; ic++) {
        const float* ipc = ip + ic * (H1 * H1) + oy * 36 + ox * 2;  // (2*oy)*18 + 2*ox
        const float* wr  = wp + ic * 9;
        #pragma unroll
        for (int ky = 0; ky < 3; ky++) {
            const float* row = ipc + ky * H1;
            #pragma unroll
            for (int kx = 0; kx < 3; kx++) s += row[kx] * wr[ky * 3 + kx];
        }
    }
    out[idx] = fmaxf(s, 0.f);
}

// ---------------- generic tiled SGEMM: C[M,N] = act(A[M,K] @ B[N,K]^T + bias) ----------------
// 64x64 tile, BK=16, 256 threads, 4x4 microtile. Requires M%64==0, N%64==0, K%16==0, lda/ldb%4==0.
__global__ void k_gemm_abt(const float* __restrict__ A, int lda,
                           const float* __restrict__ B, int ldb,
                           const float* __restrict__ bias,
                           float* __restrict__ C, int ldc,
                           int K, int act) {
    __shared__ float As[16][68];
    __shared__ float Bs[16][68];
    int m0 = blockIdx.y * 64, n0 = blockIdx.x * 64;
    int tid = threadIdx.x;
    int tr = tid / 16, tc = tid % 16;
    int lrow = tid >> 2, lkg = (tid & 3) * 4;
    float acc[4][4] = {};
    for (int k0 = 0; k0 < K; k0 += 16) {
        float4 av = *(const float4*)(A + (size_t)(m0 + lrow) * lda + k0 + lkg);
        float4 bv = *(const float4*)(B + (size_t)(n0 + lrow) * ldb + k0 + lkg);
        As[lkg + 0][lrow] = av.x; As[lkg + 1][lrow] = av.y;
        As[lkg + 2][lrow] = av.z; As[lkg + 3][lrow] = av.w;
        Bs[lkg + 0][lrow] = bv.x; Bs[lkg + 1][lrow] = bv.y;
        Bs[lkg + 2][lrow] = bv.z; Bs[lkg + 3][lrow] = bv.w;
        __syncthreads();
        #pragma unroll
        for (int k = 0; k < 16; k++) {
            float4 a = *(const float4*)&As[k][tr * 4];
            float4 b = *(const float4*)&Bs[k][tc * 4];
            acc[0][0] += a.x * b.x; acc[0][1] += a.x * b.y; acc[0][2] += a.x * b.z; acc[0][3] += a.x * b.w;
            acc[1][0] += a.y * b.x; acc[1][1] += a.y * b.y; acc[1][2] += a.y * b.z; acc[1][3] += a.y * b.w;
            acc[2][0] += a.z * b.x; acc[2][1] += a.z * b.y; acc[2][2] += a.z * b.z; acc[2][3] += a.z * b.w;
            acc[3][0] += a.w * b.x; acc[3][1] += a.w * b.y; acc[3][2] += a.w * b.z; acc[3][3] += a.w * b.w;
        }
        __syncthreads();
    }
    #pragma unroll
    for (int i = 0; i < 4; i++) {
        int row = m0 + tr * 4 + i;
        #pragma unroll
        for (int j = 0; j < 4; j++) {
            int col = n0 + tc * 4 + j;
            float v = acc[i][j] + bias[col];
            if (act == 1) v = fmaxf(v, 0.f);
            C[(size_t)row * ldc + col] = v;
        }
    }
}

// ---------------- embedding into g_feat[:,128:144] ----------------
__global__ void k_embed(const int* __restrict__ cls, const float* __restrict__ table,
                        float* __restrict__ feat) {
    int idx = blockIdx.x * 256 + threadIdx.x;
    if (idx >= NB * 16) return;
    int i = idx >> 4, j = idx & 15;
    int id = g_isI32 ? cls[i] : cls[2 * i];   // int64 little-endian low word
    feat[i * FEAT + 128 + j] = table[id * 16 + j];
}

// ---------------- GRU gate fusion ----------------
__global__ void k_gru(const float* __restrict__ gi, const float* __restrict__ gh,
                      const float* __restrict__ h, float* __restrict__ nh) {
    int idx = blockIdx.x * 256 + threadIdx.x;
    if (idx >= NB * HD) return;
    int i = idx >> 7, j = idx & 127;
    const float* a = gi + i * G3H;
    const float* c = gh + i * G3H;
    float r = 1.f / (1.f + __expf(-(a[j] + c[j])));
    float z = 1.f / (1.f + __expf(-(a[128 + j] + c[128 + j])));
    float n = tanhf(a[256 + j] + r * c[256 + j]);
    nh[idx] = (1.f - z) * n + z * h[idx];
}

// ---------------- fused masked flash attention ----------------
// 64-row blocks; per column tile: S=Q*K^T (swizzled smem GEMM), mask from adjacency,
// online softmax (finite -1e9 mask, matching jnp.where semantics), O += P*V.
#define SWZ(c4, rhi) ((((c4) ^ (rhi)) & 31) * 4)
__global__ void k_attn(const float* __restrict__ Q, const float* __restrict__ Km,
                       const float* __restrict__ V, const int* __restrict__ adj,
                       float* __restrict__ ctx) {
    extern __shared__ float sm[];
    float* Qs   = sm;             // 64*128 (swizzled)
    float* Ks   = Qs + 8192;      // 64*128 (swizzled)
    float* Vs   = Ks + 8192;      // 64*128 (swizzled)
    float* Ss   = Vs + 8192;      // 64*65
    float* m_sh = Ss + 64 * 65;   // 64
    float* l_sh = m_sh + 64;      // 64
    float* a_sh = l_sh + 64;      // 64
    int*   adjs = (int*)(a_sh + 64);  // 64*64

    int tid  = threadIdx.x;
    int row0 = blockIdx.x * 64;
    int tr  = tid / 16, tc  = tid % 16;   // S-GEMM mapping (4x4)
    int tr2 = tid / 32, tc2 = tid % 32;   // O mapping (8 rows x 4 cols)

    // load Q tile (swizzled)
    {
        const float4* src = (const float4*)(Q + (size_t)row0 * 128);
        #pragma unroll
        for (int t = 0; t < 8; t++) {
            int p = tid + t * 256;          // float4 id
            int r = p >> 5, c4 = p & 31;
            *(float4*)(Qs + r * 128 + SWZ(c4, r >> 2)) = src[p];
        }
    }
    if (tid < 64) { m_sh[tid] = -1e30f; l_sh[tid] = 0.f; }
    float oacc[8][4];
    #pragma unroll
    for (int i = 0; i < 8; i++)
        #pragma unroll
        for (int j = 0; j < 4; j++) oacc[i][j] = 0.f;
    __syncthreads();

    const float scale = 0.08838834764831845f;  // 1/sqrt(128)

    for (int c0 = 0; c0 < NB; c0 += 64) {
        // load K/V tiles (swizzled) + adjacency tile
        {
            const float4* sK = (const float4*)(Km + (size_t)c0 * 128);
            const float4* sV = (const float4*)(V  + (size_t)c0 * 128);
            #pragma unroll
            for (int t = 0; t < 8; t++) {
                int p = tid + t * 256;
                int r = p >> 5, c4 = p & 31;
                *(float4*)(Ks + r * 128 + SWZ(c4, r >> 2)) = sK[p];
                *(float4*)(Vs + r * 128 + SWZ(c4, r >> 2)) = sV[p];
            }
            #pragma unroll
            for (int t = 0; t < 4; t++) {
                int p = tid + t * 256;          // int4 id, 0..1023
                int r = p >> 4, c4 = p & 15;
                ((int4*)adjs)[p] = *(const int4*)(adj + (size_t)(row0 + r) * NB + c0 + c4 * 4);
            }
        }
        __syncthreads();

        // S = Qs * Ks^T
        float sacc[4][4] = {};
        #pragma unroll 8
        for (int kk = 0; kk < 32; kk++) {
            float4 a0 = *(const float4*)(Qs + (4 * tr + 0) * 128 + SWZ(kk, tr));
            float4 a1 = *(const float4*)(Qs + (4 * tr + 1) * 128 + SWZ(kk, tr));
            float4 a2 = *(const float4*)(Qs + (4 * tr + 2) * 128 + SWZ(kk, tr));
            float4 a3 = *(const float4*)(Qs + (4 * tr + 3) * 128 + SWZ(kk, tr));
            float4 b0 = *(const float4*)(Ks + (4 * tc + 0) * 128 + SWZ(kk, tc));
            float4 b1 = *(const float4*)(Ks + (4 * tc + 1) * 128 + SWZ(kk, tc));
            float4 b2 = *(const float4*)(Ks + (4 * tc + 2) * 128 + SWZ(kk, tc));
            float4 b3 = *(const float4*)(Ks + (4 * tc + 3) * 128 + SWZ(kk, tc));
            sacc[0][0] += a0.x*b0.x + a0.y*b0.y + a0.z*b0.z + a0.w*b0.w;
            sacc[0][1] += a0.x*b1.x + a0.y*b1.y + a0.z*b1.z + a0.w*b1.w;
            sacc[0][2] += a0.x*b2.x + a0.y*b2.y + a0.z*b2.z + a0.w*b2.w;
            sacc[0][3] += a0.x*b3.x + a0.y*b3.y + a0.z*b3.z + a0.w*b3.w;
            sacc[1][0] += a1.x*b0.x + a1.y*b0.y + a1.z*b0.z + a1.w*b0.w;
            sacc[1][1] += a1.x*b1.x + a1.y*b1.y + a1.z*b1.z + a1.w*b1.w;
            sacc[1][2] += a1.x*b2.x + a1.y*b2.y + a1.z*b2.z + a1.w*b2.w;
            sacc[1][3] += a1.x*b3.x + a1.y*b3.y + a1.z*b3.z + a1.w*b3.w;
            sacc[2][0] += a2.x*b0.x + a2.y*b0.y + a2.z*b0.z + a2.w*b0.w;
            sacc[2][1] += a2.x*b1.x + a2.y*b1.y + a2.z*b1.z + a2.w*b1.w;
            sacc[2][2] += a2.x*b2.x + a2.y*b2.y + a2.z*b2.z + a2.w*b2.w;
            sacc[2][3] += a2.x*b3.x + a2.y*b3.y + a2.z*b3.z + a2.w*b3.w;
            sacc[3][0] += a3.x*b0.x + a3.y*b0.y + a3.z*b0.z + a3.w*b0.w;
            sacc[3][1] += a3.x*b1.x + a3.y*b1.y + a3.z*b1.z + a3.w*b1.w;
            sacc[3][2] += a3.x*b2.x + a3.y*b2.y + a3.z*b2.z + a3.w*b2.w;
            sacc[3][3] += a3.x*b3.x + a3.y*b3.y + a3.z*b3.z + a3.w*b3.w;
        }
        #pragma unroll
        for (int i = 0; i < 4; i++)
            #pragma unroll
            for (int j = 0; j < 4; j++)
                Ss[(4 * tr + i) * 65 + 4 * tc + j] = sacc[i][j] * scale;
        __syncthreads();

        // online softmax (one thread per row)
        if (tid < 64) {
            int r = tid;
            float m_old = m_sh[r];
            float mt = -1e30f;
            #pragma unroll 8
            for (int j = 0; j < 64; j++) {
                float s = Ss[r * 65 + j];
                if (adjs[r * 64 + j] == 0) s = -1e9f;
                Ss[r * 65 + j] = s;
                mt = fmaxf(mt, s);
            }
            float mn = fmaxf(m_old, mt);
            float alpha = __expf(m_old - mn);
            float l = l_sh[r] * alpha;
            #pragma unroll 8
            for (int j = 0; j < 64; j++) {
                float p = __expf(Ss[r * 65 + j] - mn);
                Ss[r * 65 + j] = p;
                l += p;
            }
            m_sh[r] = mn; l_sh[r] = l; a_sh[r] = alpha;
        }
        __syncthreads();

        // O = alpha*O + P @ V
        #pragma unroll
        for (int i = 0; i < 8; i++) {
            float a = a_sh[tr2 * 8 + i];
            #pragma unroll
            for (int j = 0; j < 4; j++) oacc[i][j] *= a;
        }
        #pragma unroll 4
        for (int k = 0; k < 64; k++) {
            float4 b = *(const float4*)(Vs + k * 128 + SWZ(tc2, k >> 2));
            #pragma unroll
            for (int i = 0; i < 8; i++) {
                float a = Ss[(tr2 * 8 + i) * 65 + k];
                oacc[i][0] += a * b.x; oacc[i][1] += a * b.y;
                oacc[i][2] += a * b.z; oacc[i][3] += a * b.w;
            }
        }
        __syncthreads();
    }

    // epilogue: O /= l
    #pragma unroll
    for (int i = 0; i < 8; i++) {
        float inv = 1.f / l_sh[tr2 * 8 + i];
        float4 o;
        o.x = oacc[i][0] * inv; o.y = oacc[i][1] * inv;
        o.z = oacc[i][2] * inv; o.w = oacc[i][3] * inv;
        *(float4*)(ctx + (size_t)(row0 + tr2 * 8 + i) * 128 + tc2 * 4) = o;
    }
}

// ---------------- final head: q = [nh, swarm] @ fcq_w^T + b ----------------
__global__ void k_fcq(const float* __restrict__ nh, const float* __restrict__ sw,
                      const float* __restrict__ W, const float* __restrict__ b,
                      float* __restrict__ q) {
    int idx = blockIdx.x * 256 + threadIdx.x;
    if (idx >= NB * 5) return;
    int i = idx / 5, a = idx % 5;
    const float* w = W + a * 256;
    const float* hr = nh + i * 128;
    const float* sr = sw + i * 128;
    float s = b[a];
    #pragma unroll 8
    for (int k = 0; k < 128; k++) s += hr[k] * w[k];
    #pragma unroll 8
    for (int k = 0; k < 128; k++) s += sr[k] * w[128 + k];
    q[idx] = s;
}

// ---------------- launch ----------------
extern "C" void kernel_launch(void* const* d_in, const int* in_sizes, int n_in,
                              void* d_out, int out_size) {
    const float* img    = (const float*)d_in[0];
    const int*   adj    = (const int*)  d_in[1];
    const int*   cls    = (const int*)  d_in[2];
    const float* h0     = (const float*)d_in[3];
    const float* c1w    = (const float*)d_in[4];
    const float* c1b    = (const float*)d_in[5];
    const float* c2w    = (const float*)d_in[6];
    const float* c2b    = (const float*)d_in[7];
    const float* fvw    = (const float*)d_in[8];
    const float* fvb    = (const float*)d_in[9];
    const float* emb    = (const float*)d_in[10];
    const float* wih    = (const float*)d_in[11];
    const float* whh    = (const float*)d_in[12];
    const float* bih    = (const float*)d_in[13];
    const float* bhh    = (const float*)d_in[14];
    const float* wqw    = (const float*)d_in[15];
    const float* wqb    = (const float*)d_in[16];
    const float* wkw    = (const float*)d_in[17];
    const float* wkb    = (const float*)d_in[18];
    const float* wvw    = (const float*)d_in[19];
    const float* wvb    = (const float*)d_in[20];
    const float* aow    = (const float*)d_in[21];
    const float* aob    = (const float*)d_in[22];
    const float* fqw    = (const float*)d_in[23];
    const float* fqb    = (const float*)d_in[24];

    float* qout = (float*)d_out;          // [8192,5]
    float* nh   = qout + NB * 5;          // [8192,128] new_hidden

    float *pc1, *pflat, *pfeat, *pgi, *pgh, *pQ, *pK, *pV, *pctx, *pswarm;
    cudaGetSymbolAddress((void**)&pc1,    g_conv1);
    cudaGetSymbolAddress((void**)&pflat,  g_flat);
    cudaGetSymbolAddress((void**)&pfeat,  g_feat);
    cudaGetSymbolAddress((void**)&pgi,    g_gi);
    cudaGetSymbolAddress((void**)&pgh,    g_gh);
    cudaGetSymbolAddress((void**)&pQ,     g_Q);
    cudaGetSymbolAddress((void**)&pK,     g_K);
    cudaGetSymbolAddress((void**)&pV,     g_V);
    cudaGetSymbolAddress((void**)&pctx,   g_ctx);
    cudaGetSymbolAddress((void**)&pswarm, g_swarm);

    // class-id dtype detection
    k_flag_init<<<1, 1>>>();
    k_flag_detect<<<16, 256>>>(cls);

    // CNN encoder
    k_conv1<<<(NB * C1O * H1 * H1) / 256, 256>>>(img, c1w, c1b, pc1);
    k_conv2<<<(NB * FLAT) / 256, 256>>>(pc1, c2w, c2b, pflat);

    // vis_feat = relu(flat @ fc_vis_w^T + b) written into g_feat[:, :128]
    { dim3 g(128 / 64, NB / 64); k_gemm_abt<<<g, 256>>>(pflat, FLAT, fvw, FLAT, fvb, pfeat, FEAT, FLAT, 1); }
    // cls embedding -> g_feat[:, 128:144]
    k_embed<<<(NB * 16) / 256, 256>>>(cls, emb, pfeat);

    // GRU
    { dim3 g(G3H / 64, NB / 64); k_gemm_abt<<<g, 256>>>(pfeat, FEAT, wih, FEAT, bih, pgi, G3H, FEAT, 0); }
    { dim3 g(G3H / 64, NB / 64); k_gemm_abt<<<g, 256>>>(h0,    HD,   whh, HD,   bhh, pgh, G3H, HD,   0); }
    k_gru<<<(NB * HD) / 256, 256>>>(pgi, pgh, h0, nh);

    // Q, K, V projections
    { dim3 g(HD / 64, NB / 64); k_gemm_abt<<<g, 256>>>(nh, HD, wqw, HD, wqb, pQ, HD, HD, 0); }
    { dim3 g(HD / 64, NB / 64); k_gemm_abt<<<g, 256>>>(nh, HD, wkw, HD, wkb, pK, HD, HD, 0); }
    { dim3 g(HD / 64, NB / 64); k_gemm_abt<<<g, 256>>>(nh, HD, wvw, HD, wvb, pV, HD, HD, 0); }

    // fused masked attention
    const int attn_smem = (8192 * 3 + 64 * 65 + 192) * 4 + 64 * 64 * 4;   // 132096 B
    cudaFuncSetAttribute(k_attn, cudaFuncAttributeMaxDynamicSharedMemorySize, attn_smem);
    k_attn<<<NB / 64, 256, attn_smem>>>(pQ, pK, pV, adj, pctx);

    // attention output projection
    { dim3 g(HD / 64, NB / 64); k_gemm_abt<<<g, 256>>>(pctx, HD, aow, HD, aob, pswarm, HD, HD, 0); }

    // final Q-values
    k_fcq<<<(NB * 5 + 255) / 256, 256>>>(nh, pswarm, fqw, fqb, qout);
}

// round 2
// speedup vs baseline: 2.1851x; 2.1851x over previous
#include <cuda_runtime.h>
#include <math.h>

// ---------------- problem dims ----------------
#define NB    8192          // batch / num agents
#define HD    128           // hidden
#define C1O   16
#define H1    18            // (40-5)/2+1
#define C2O   32
#define H2    8             // (18-3)/2+1
#define FLAT  2048          // 32*8*8
#define FEAT  144           // 128 + 16
#define G3H   384           // 3*H

// ---------------- scratch (device globals; no allocations allowed) ----------------
__device__ float g_conv1[NB * C1O * H1 * H1];
__device__ float g_flat [NB * FLAT];
__device__ float g_feat [NB * FEAT];
__device__ float g_gi   [NB * G3H];
__device__ float g_gh   [NB * G3H];
__device__ float g_Q    [NB * HD];
__device__ float g_K    [NB * HD];
__device__ float g_V    [NB * HD];
__device__ float g_ctx  [NB * HD];
__device__ float g_swarm[NB * HD];
__device__ int   g_isI32;

// ---------------- class_ids dtype detection ----------------
__global__ void k_flag_init() { g_isI32 = 0; }
__global__ void k_flag_detect(const int* __restrict__ p) {
    int i = blockIdx.x * blockDim.x + threadIdx.x;   // i < 4096
    if (i < 4096 && p[2 * i + 1] != 0) g_isI32 = 1;
}

// ---------------- conv1: [N,3,40,40] -> relu -> [N,16,18,18], stride 2, 5x5 ----------------
// One thread per spatial output position; computes all 16 output channels.
// Weights in smem transposed to [k75][oc16] so inner reads are 4x LDS.128 broadcast.
__global__ void k_conv1(const float* __restrict__ img, const float* __restrict__ w,
                        const float* __restrict__ b, float* __restrict__ out) {
    __shared__ float ws[75 * 16];
    __shared__ float bs[16];
    for (int i = threadIdx.x; i < 1200; i += 256) {
        int oc = i / 75, k = i % 75;
        ws[k * 16 + oc] = w[i];
    }
    if (threadIdx.x < 16) bs[threadIdx.x] = b[threadIdx.x];
    __syncthreads();

    int idx = blockIdx.x * 256 + threadIdx.x;        // exact: 8192*324 / 256 blocks
    int ox = idx % H1;
    int oy = (idx / H1) % H1;
    int n  = idx / (H1 * H1);
    const float* ip = img + (size_t)n * 4800;

    float acc[16];
    #pragma unroll
    for (int oc = 0; oc < 16; oc++) acc[oc] = bs[oc];

    #pragma unroll
    for (int ic = 0; ic < 3; ic++) {
        const float* basep = ip + ic * 1600 + oy * 80 + ox * 2;
        #pragma unroll
        for (int ky = 0; ky < 5; ky++) {
            const float* row = basep + ky * 40;
            #pragma unroll
            for (int kx = 0; kx < 5; kx++) {
                float v = row[kx];
                const float4* wp = (const float4*)&ws[((ic * 5 + ky) * 5 + kx) * 16];
                float4 w0 = wp[0], w1 = wp[1], w2 = wp[2], w3 = wp[3];
                acc[0]  += v * w0.x; acc[1]  += v * w0.y; acc[2]  += v * w0.z; acc[3]  += v * w0.w;
                acc[4]  += v * w1.x; acc[5]  += v * w1.y; acc[6]  += v * w1.z; acc[7]  += v * w1.w;
                acc[8]  += v * w2.x; acc[9]  += v * w2.y; acc[10] += v * w2.z; acc[11] += v * w2.w;
                acc[12] += v * w3.x; acc[13] += v * w3.y; acc[14] += v * w3.z; acc[15] += v * w3.w;
            }
        }
    }
    float* op = out + (size_t)n * (16 * 324) + oy * H1 + ox;
    #pragma unroll
    for (int oc = 0; oc < 16; oc++) op[oc * 324] = fmaxf(acc[oc], 0.f);
}

// ---------------- conv2: [N,16,18,18] -> relu -> flat [N,2048], stride 2, 3x3 ----------------
// One thread per spatial output position; computes all 32 output channels.
__global__ void k_conv2(const float* __restrict__ in, const float* __restrict__ w,
                        const float* __restrict__ b, float* __restrict__ out) {
    __shared__ float ws[144 * 32];   // [k144][oc32]
    __shared__ float bs[32];
    for (int i = threadIdx.x; i < 4608; i += 256) {
        int oc = i / 144, k = i % 144;
        ws[k * 32 + oc] = w[i];
    }
    if (threadIdx.x < 32) bs[threadIdx.x] = b[threadIdx.x];
    __syncthreads();

    int idx = blockIdx.x * 256 + threadIdx.x;        // exact: 8192*64 / 256 blocks
    int ox = idx % H2;
    int oy = (idx / H2) % H2;
    int n  = idx / (H2 * H2);
    const float* ip = in + (size_t)n * (16 * 324);

    float acc[32];
    #pragma unroll
    for (int oc = 0; oc < 32; oc++) acc[oc] = bs[oc];

    #pragma unroll 4
    for (int ic = 0; ic < 16; ic++) {
        const float* basep = ip + ic * 324 + oy * 36 + ox * 2;
        #pragma unroll
        for (int ky = 0; ky < 3; ky++) {
            const float* row = basep + ky * H1;
            #pragma unroll
            for (int kx = 0; kx < 3; kx++) {
                float v = row[kx];
                const float4* wp = (const float4*)&ws[((ic * 9) + ky * 3 + kx) * 32];
                #pragma unroll
                for (int g = 0; g < 8; g++) {
                    float4 wv = wp[g];
                    acc[g * 4 + 0] += v * wv.x;
                    acc[g * 4 + 1] += v * wv.y;
                    acc[g * 4 + 2] += v * wv.z;
                    acc[g * 4 + 3] += v * wv.w;
                }
            }
        }
    }
    float* op = out + (size_t)n * FLAT + oy * H2 + ox;
    #pragma unroll
    for (int oc = 0; oc < 32; oc++) op[oc * 64] = fmaxf(acc[oc], 0.f);
}

// ---------------- generic tiled SGEMM: C[M,N] = act(A[M,K] @ B[N,K]^T + bias) ----------------
__global__ void k_gemm_abt(const float* __restrict__ A, int lda,
                           const float* __restrict__ B, int ldb,
                           const float* __restrict__ bias,
                           float* __restrict__ C, int ldc,
                           int K, int act) {
    __shared__ float As[16][68];
    __shared__ float Bs[16][68];
    int m0 = blockIdx.y * 64, n0 = blockIdx.x * 64;
    int tid = threadIdx.x;
    int tr = tid / 16, tc = tid % 16;
    int lrow = tid >> 2, lkg = (tid & 3) * 4;
    float acc[4][4] = {};
    for (int k0 = 0; k0 < K; k0 += 16) {
        float4 av = *(const float4*)(A + (size_t)(m0 + lrow) * lda + k0 + lkg);
        float4 bv = *(const float4*)(B + (size_t)(n0 + lrow) * ldb + k0 + lkg);
        As[lkg + 0][lrow] = av.x; As[lkg + 1][lrow] = av.y;
        As[lkg + 2][lrow] = av.z; As[lkg + 3][lrow] = av.w;
        Bs[lkg + 0][lrow] = bv.x; Bs[lkg + 1][lrow] = bv.y;
        Bs[lkg + 2][lrow] = bv.z; Bs[lkg + 3][lrow] = bv.w;
        __syncthreads();
        #pragma unroll
        for (int k = 0; k < 16; k++) {
            float4 a = *(const float4*)&As[k][tr * 4];
            float4 b = *(const float4*)&Bs[k][tc * 4];
            acc[0][0] += a.x * b.x; acc[0][1] += a.x * b.y; acc[0][2] += a.x * b.z; acc[0][3] += a.x * b.w;
            acc[1][0] += a.y * b.x; acc[1][1] += a.y * b.y; acc[1][2] += a.y * b.z; acc[1][3] += a.y * b.w;
            acc[2][0] += a.z * b.x; acc[2][1] += a.z * b.y; acc[2][2] += a.z * b.z; acc[2][3] += a.z * b.w;
            acc[3][0] += a.w * b.x; acc[3][1] += a.w * b.y; acc[3][2] += a.w * b.z; acc[3][3] += a.w * b.w;
        }
        __syncthreads();
    }
    #pragma unroll
    for (int i = 0; i < 4; i++) {
        int row = m0 + tr * 4 + i;
        #pragma unroll
        for (int j = 0; j < 4; j++) {
            int col = n0 + tc * 4 + j;
            float v = acc[i][j] + bias[col];
            if (act == 1) v = fmaxf(v, 0.f);
            C[(size_t)row * ldc + col] = v;
        }
    }
}

// ---------------- embedding into g_feat[:,128:144] ----------------
__global__ void k_embed(const int* __restrict__ cls, const float* __restrict__ table,
                        float* __restrict__ feat) {
    int idx = blockIdx.x * 256 + threadIdx.x;
    if (idx >= NB * 16) return;
    int i = idx >> 4, j = idx & 15;
    int id = g_isI32 ? cls[i] : cls[2 * i];
    feat[i * FEAT + 128 + j] = table[id * 16 + j];
}

// ---------------- GRU gate fusion ----------------
__global__ void k_gru(const float* __restrict__ gi, const float* __restrict__ gh,
                      const float* __restrict__ h, float* __restrict__ nh) {
    int idx = blockIdx.x * 256 + threadIdx.x;
    if (idx >= NB * HD) return;
    int i = idx >> 7, j = idx & 127;
    const float* a = gi + i * G3H;
    const float* c = gh + i * G3H;
    float r = 1.f / (1.f + __expf(-(a[j] + c[j])));
    float z = 1.f / (1.f + __expf(-(a[128 + j] + c[128 + j])));
    float n = tanhf(a[256 + j] + r * c[256 + j]);
    nh[idx] = (1.f - z) * n + z * h[idx];
}

// ---------------- fused masked flash attention ----------------
// 64-row CTA (grid 128), 256 threads. Per 64-col tile: S = Q*K^T via swizzled smem
// GEMM (4x4 microtile), adjacency loaded directly from GMEM, fully parallel online
// softmax with m/l/alpha replicated in registers across each 16-lane row group,
// O (4x8 microtile) accumulated from P (smem, warp-private rows) and V.
__global__ void k_attn(const float* __restrict__ Q, const float* __restrict__ Km,
                       const float* __restrict__ V, const int* __restrict__ adj,
                       float* __restrict__ ctx) {
    extern __shared__ float sm[];
    float* Qs = sm;               // 64*128 swizzled
    float* Ks = Qs + 8192;        // 64*128 swizzled
    float* Vs = Ks + 8192;        // 64*128 swizzled
    float* Ss = Vs + 8192;        // 64*64 (P tile)

    int tid = threadIdx.x;
    int row0 = blockIdx.x * 64;
    int tr = tid >> 4, tc = tid & 15;    // rows 4tr..4tr+3, S-cols 4tc..4tc+3, O-cols 8tc..8tc+7

    // load Q tile (swizzled)
    {
        const float4* src = (const float4*)(Q + (size_t)row0 * 128);
        #pragma unroll
        for (int t = 0; t < 8; t++) {
            int p = tid + t * 256;
            int r = p >> 5, c4 = p & 31;
            *(float4*)(Qs + r * 128 + (((c4 ^ (r >> 2)) & 31) << 2)) = src[p];
        }
    }
    float m[4], l[4];
    #pragma unroll
    for (int i = 0; i < 4; i++) { m[i] = -1e30f; l[i] = 0.f; }
    float oacc[4][8];
    #pragma unroll
    for (int i = 0; i < 4; i++)
        #pragma unroll
        for (int j = 0; j < 8; j++) oacc[i][j] = 0.f;
    __syncthreads();

    const float scale = 0.08838834764831845f;  // 1/sqrt(128)

    for (int c0 = 0; c0 < NB; c0 += 64) {
        // load K/V tiles (swizzled)
        {
            const float4* sK = (const float4*)(Km + (size_t)c0 * 128);
            const float4* sV = (const float4*)(V  + (size_t)c0 * 128);
            #pragma unroll
            for (int t = 0; t < 8; t++) {
                int p = tid + t * 256;
                int r = p >> 5, c4 = p & 31;
                int off = r * 128 + (((c4 ^ (r >> 2)) & 31) << 2);
                *(float4*)(Ks + off) = sK[p];
                *(float4*)(Vs + off) = sV[p];
            }
        }
        __syncthreads();

        // S = Qs * Ks^T  (4x4 microtile over K=128)
        float sacc[4][4] = {};
        #pragma unroll 8
        for (int kk = 0; kk < 32; kk++) {
            float4 a0 = *(const float4*)(Qs + (4 * tr + 0) * 128 + (((kk ^ tr) & 31) << 2));
            float4 a1 = *(const float4*)(Qs + (4 * tr + 1) * 128 + (((kk ^ tr) & 31) << 2));
            float4 a2 = *(const float4*)(Qs + (4 * tr + 2) * 128 + (((kk ^ tr) & 31) << 2));
            float4 a3 = *(const float4*)(Qs + (4 * tr + 3) * 128 + (((kk ^ tr) & 31) << 2));
            float4 b0 = *(const float4*)(Ks + (4 * tc + 0) * 128 + (((kk ^ tc) & 31) << 2));
            float4 b1 = *(const float4*)(Ks + (4 * tc + 1) * 128 + (((kk ^ tc) & 31) << 2));
            float4 b2 = *(const float4*)(Ks + (4 * tc + 2) * 128 + (((kk ^ tc) & 31) << 2));
            float4 b3 = *(const float4*)(Ks + (4 * tc + 3) * 128 + (((kk ^ tc) & 31) << 2));
            sacc[0][0] += a0.x*b0.x + a0.y*b0.y + a0.z*b0.z + a0.w*b0.w;
            sacc[0][1] += a0.x*b1.x + a0.y*b1.y + a0.z*b1.z + a0.w*b1.w;
            sacc[0][2] += a0.x*b2.x + a0.y*b2.y + a0.z*b2.z + a0.w*b2.w;
            sacc[0][3] += a0.x*b3.x + a0.y*b3.y + a0.z*b3.z + a0.w*b3.w;
            sacc[1][0] += a1.x*b0.x + a1.y*b0.y + a1.z*b0.z + a1.w*b0.w;
            sacc[1][1] += a1.x*b1.x + a1.y*b1.y + a1.z*b1.z + a1.w*b1.w;
            sacc[1][2] += a1.x*b2.x + a1.y*b2.y + a1.z*b2.z + a1.w*b2.w;
            sacc[1][3] += a1.x*b3.x + a1.y*b3.y + a1.z*b3.z + a1.w*b3.w;
            sacc[2][0] += a2.x*b0.x + a2.y*b0.y + a2.z*b0.z + a2.w*b0.w;
            sacc[2][1] += a2.x*b1.x + a2.y*b1.y + a2.z*b1.z + a2.w*b1.w;
            sacc[2][2] += a2.x*b2.x + a2.y*b2.y + a2.z*b2.z + a2.w*b2.w;
            sacc[2][3] += a2.x*b3.x + a2.y*b3.y + a2.z*b3.z + a2.w*b3.w;
            sacc[3][0] += a3.x*b0.x + a3.y*b0.y + a3.z*b0.z + a3.w*b0.w;
            sacc[3][1] += a3.x*b1.x + a3.y*b1.y + a3.z*b1.z + a3.w*b1.w;
            sacc[3][2] += a3.x*b2.x + a3.y*b2.y + a3.z*b2.z + a3.w*b2.w;
            sacc[3][3] += a3.x*b3.x + a3.y*b3.y + a3.z*b3.z + a3.w*b3.w;
        }

        // mask (direct gmem adjacency) + parallel online softmax
        float p[4][4], mt[4], rs[4], alpha[4];
        #pragma unroll
        for (int i = 0; i < 4; i++) {
            int4 av = *(const int4*)(adj + (size_t)(row0 + 4 * tr + i) * NB + c0 + 4 * tc);
            p[i][0] = av.x ? sacc[i][0] * scale : -1e9f;
            p[i][1] = av.y ? sacc[i][1] * scale : -1e9f;
            p[i][2] = av.z ? sacc[i][2] * scale : -1e9f;
            p[i][3] = av.w ? sacc[i][3] * scale : -1e9f;
            mt[i] = fmaxf(fmaxf(p[i][0], p[i][1]), fmaxf(p[i][2], p[i][3]));
        }
        #pragma unroll
        for (int off = 8; off > 0; off >>= 1) {
            #pragma unroll
            for (int i = 0; i < 4; i++)
                mt[i] = fmaxf(mt[i], __shfl_xor_sync(0xffffffffu, mt[i], off, 16));
        }
        #pragma unroll
        for (int i = 0; i < 4; i++) {
            float mn = fmaxf(m[i], mt[i]);
            alpha[i] = __expf(m[i] - mn);
            m[i] = mn;
            p[i][0] = __expf(p[i][0] - mn);
            p[i][1] = __expf(p[i][1] - mn);
            p[i][2] = __expf(p[i][2] - mn);
            p[i][3] = __expf(p[i][3] - mn);
            rs[i] = (p[i][0] + p[i][1]) + (p[i][2] + p[i][3]);
        }
        #pragma unroll
        for (int off = 8; off > 0; off >>= 1) {
            #pragma unroll
            for (int i = 0; i < 4; i++)
                rs[i] += __shfl_xor_sync(0xffffffffu, rs[i], off, 16);
        }
        #pragma unroll
        for (int i = 0; i < 4; i++) {
            l[i] = l[i] * alpha[i] + rs[i];
            *(float4*)(Ss + (4 * tr + i) * 64 + 4 * tc) =
                make_float4(p[i][0], p[i][1], p[i][2], p[i][3]);
        }
        __syncwarp();

        // O = alpha*O + P @ V
        #pragma unroll
        for (int i = 0; i < 4; i++)
            #pragma unroll
            for (int j = 0; j < 8; j++) oacc[i][j] *= alpha[i];

        #pragma unroll 4
        for (int k = 0; k < 64; k++) {
            float4 v0 = *(const float4*)(Vs + k * 128 + ((((2 * tc)     ^ (k >> 2)) & 31) << 2));
            float4 v1 = *(const float4*)(Vs + k * 128 + ((((2 * tc + 1) ^ (k >> 2)) & 31) << 2));
            float pr0 = Ss[(4 * tr + 0) * 64 + k];
            float pr1 = Ss[(4 * tr + 1) * 64 + k];
            float pr2 = Ss[(4 * tr + 2) * 64 + k];
            float pr3 = Ss[(4 * tr + 3) * 64 + k];
            oacc[0][0] += pr0 * v0.x; oacc[0][1] += pr0 * v0.y; oacc[0][2] += pr0 * v0.z; oacc[0][3] += pr0 * v0.w;
            oacc[0][4] += pr0 * v1.x; oacc[0][5] += pr0 * v1.y; oacc[0][6] += pr0 * v1.z; oacc[0][7] += pr0 * v1.w;
            oacc[1][0] += pr1 * v0.x; oacc[1][1] += pr1 * v0.y; oacc[1][2] += pr1 * v0.z; oacc[1][3] += pr1 * v0.w;
            oacc[1][4] += pr1 * v1.x; oacc[1][5] += pr1 * v1.y; oacc[1][6] += pr1 * v1.z; oacc[1][7] += pr1 * v1.w;
            oacc[2][0] += pr2 * v0.x; oacc[2][1] += pr2 * v0.y; oacc[2][2] += pr2 * v0.z; oacc[2][3] += pr2 * v0.w;
            oacc[2][4] += pr2 * v1.x; oacc[2][5] += pr2 * v1.y; oacc[2][6] += pr2 * v1.z; oacc[2][7] += pr2 * v1.w;
            oacc[3][0] += pr3 * v0.x; oacc[3][1] += pr3 * v0.y; oacc[3][2] += pr3 * v0.z; oacc[3][3] += pr3 * v0.w;
            oacc[3][4] += pr3 * v1.x; oacc[3][5] += pr3 * v1.y; oacc[3][6] += pr3 * v1.z; oacc[3][7] += pr3 * v1.w;
        }
        __syncthreads();
    }

    // epilogue: O /= l
    #pragma unroll
    for (int i = 0; i < 4; i++) {
        float inv = 1.f / l[i];
        float4 o0 = make_float4(oacc[i][0] * inv, oacc[i][1] * inv, oacc[i][2] * inv, oacc[i][3] * inv);
        float4 o1 = make_float4(oacc[i][4] * inv, oacc[i][5] * inv, oacc[i][6] * inv, oacc[i][7] * inv);
        float* dst = ctx + (size_t)(row0 + 4 * tr + i) * 128 + 8 * tc;
        *(float4*)(dst)     = o0;
        *(float4*)(dst + 4) = o1;
    }
}

// ---------------- final head: q = [nh, swarm] @ fcq_w^T + b ----------------
__global__ void k_fcq(const float* __restrict__ nh, const float* __restrict__ sw,
                      const float* __restrict__ W, const float* __restrict__ b,
                      float* __restrict__ q) {
    int idx = blockIdx.x * 256 + threadIdx.x;
    if (idx >= NB * 5) return;
    int i = idx / 5, a = idx % 5;
    const float* w = W + a * 256;
    const float* hr = nh + i * 128;
    const float* sr = sw + i * 128;
    float s = b[a];
    #pragma unroll 8
    for (int k = 0; k < 128; k++) s += hr[k] * w[k];
    #pragma unroll 8
    for (int k = 0; k < 128; k++) s += sr[k] * w[128 + k];
    q[idx] = s;
}

// ---------------- launch ----------------
extern "C" void kernel_launch(void* const* d_in, const int* in_sizes, int n_in,
                              void* d_out, int out_size) {
    const float* img = (const float*)d_in[0];
    const int*   adj = (const int*)  d_in[1];
    const int*   cls = (const int*)  d_in[2];
    const float* h0  = (const float*)d_in[3];
    const float* c1w = (const float*)d_in[4];
    const float* c1b = (const float*)d_in[5];
    const float* c2w = (const float*)d_in[6];
    const float* c2b = (const float*)d_in[7];
    const float* fvw = (const float*)d_in[8];
    const float* fvb = (const float*)d_in[9];
    const float* emb = (const float*)d_in[10];
    const float* wih = (const float*)d_in[11];
    const float* whh = (const float*)d_in[12];
    const float* bih = (const float*)d_in[13];
    const float* bhh = (const float*)d_in[14];
    const float* wqw = (const float*)d_in[15];
    const float* wqb = (const float*)d_in[16];
    const float* wkw = (const float*)d_in[17];
    const float* wkb = (const float*)d_in[18];
    const float* wvw = (const float*)d_in[19];
    const float* wvb = (const float*)d_in[20];
    const float* aow = (const float*)d_in[21];
    const float* aob = (const float*)d_in[22];
    const float* fqw = (const float*)d_in[23];
    const float* fqb = (const float*)d_in[24];

    float* qout = (float*)d_out;          // [8192,5]
    float* nh   = qout + NB * 5;          // [8192,128] new_hidden

    float *pc1, *pflat, *pfeat, *pgi, *pgh, *pQ, *pK, *pV, *pctx, *pswarm;
    cudaGetSymbolAddress((void**)&pc1,    g_conv1);
    cudaGetSymbolAddress((void**)&pflat,  g_flat);
    cudaGetSymbolAddress((void**)&pfeat,  g_feat);
    cudaGetSymbolAddress((void**)&pgi,    g_gi);
    cudaGetSymbolAddress((void**)&pgh,    g_gh);
    cudaGetSymbolAddress((void**)&pQ,     g_Q);
    cudaGetSymbolAddress((void**)&pK,     g_K);
    cudaGetSymbolAddress((void**)&pV,     g_V);
    cudaGetSymbolAddress((void**)&pctx,   g_ctx);
    cudaGetSymbolAddress((void**)&pswarm, g_swarm);

    // class-id dtype detection
    k_flag_init<<<1, 1>>>();
    k_flag_detect<<<16, 256>>>(cls);

    // CNN encoder
    k_conv1<<<(NB * H1 * H1) / 256, 256>>>(img, c1w, c1b, pc1);   // 10368 blocks
    k_conv2<<<(NB * H2 * H2) / 256, 256>>>(pc1, c2w, c2b, pflat); // 2048 blocks

    // vis_feat = relu(flat @ fc_vis_w^T + b) into g_feat[:, :128]
    { dim3 g(128 / 64, NB / 64); k_gemm_abt<<<g, 256>>>(pflat, FLAT, fvw, FLAT, fvb, pfeat, FEAT, FLAT, 1); }
    k_embed<<<(NB * 16) / 256, 256>>>(cls, emb, pfeat);

    // GRU
    { dim3 g(G3H / 64, NB / 64); k_gemm_abt<<<g, 256>>>(pfeat, FEAT, wih, FEAT, bih, pgi, G3H, FEAT, 0); }
    { dim3 g(G3H / 64, NB / 64); k_gemm_abt<<<g, 256>>>(h0,    HD,   whh, HD,   bhh, pgh, G3H, HD,   0); }
    k_gru<<<(NB * HD) / 256, 256>>>(pgi, pgh, h0, nh);

    // Q, K, V projections
    { dim3 g(HD / 64, NB / 64); k_gemm_abt<<<g, 256>>>(nh, HD, wqw, HD, wqb, pQ, HD, HD, 0); }
    { dim3 g(HD / 64, NB / 64); k_gemm_abt<<<g, 256>>>(nh, HD, wkw, HD, wkb, pK, HD, HD, 0); }
    { dim3 g(HD / 64, NB / 64); k_gemm_abt<<<g, 256>>>(nh, HD, wvw, HD, wvb, pV, HD, HD, 0); }

    // fused masked attention
    const int attn_smem = (3 * 8192 + 64 * 64) * 4;   // 114688 B
    cudaFuncSetAttribute(k_attn, cudaFuncAttributeMaxDynamicSharedMemorySize, attn_smem);
    k_attn<<<NB / 64, 256, attn_smem>>>(pQ, pK, pV, adj, pctx);

    // attention output projection
    { dim3 g(HD / 64, NB / 64); k_gemm_abt<<<g, 256>>>(pctx, HD, aow, HD, aob, pswarm, HD, HD, 0); }

    // final Q-values
    k_fcq<<<(NB * 5 + 255) / 256, 256>>>(nh, pswarm, fqw, fqb, qout);
}

// round 6
// speedup vs baseline: 5.3520x; 2.4493x over previous
#include <cuda_runtime.h>
#include <cuda_bf16.h>
#include <cstdint>
#include <math.h>

// ---------------- problem dims ----------------
#define NB    8192
#define HD    128
#define H1    18
#define H2    8
#define FLAT  2048
#define FEAT  144
#define G3H   384

// ---------------- scratch ----------------
__device__ float g_conv1[NB * 16 * H1 * H1];
__device__ float g_flat [NB * FLAT];
__device__ float g_feat [NB * FEAT];
__device__ float g_gi   [NB * G3H];
__device__ float g_gh   [NB * G3H];
__device__ float g_Q    [NB * HD];
__device__ float g_K    [NB * HD];
__device__ float g_V    [NB * HD];
__device__ float g_ctx  [NB * HD];
__device__ float g_swarm[NB * HD];
__device__ __nv_bfloat16 g_Kb[NB * HD];      // K bf16 row-major
__device__ __nv_bfloat16 g_Vb[NB * HD];      // V bf16 row-major
__device__ float g_Opart[2 * NB * HD];       // split-KV partial O (unnormalized)
__device__ float g_lpart[2 * NB];            // split-KV partial row sums
__device__ int   g_isI32;

// ---------------- mma/ldmatrix helpers (base ISA, legal on sm_103) ----------------
__device__ __forceinline__ uint32_t smem_u32(const void* p) {
    uint32_t a;
    asm("{ .reg .u64 t; cvta.to.shared.u64 t, %1; cvt.u32.u64 %0, t; }" : "=r"(a) : "l"(p));
    return a;
}
#define LDSM_X4(r0, r1, r2, r3, a) \
    asm volatile("ldmatrix.sync.aligned.m8n8.x4.shared.b16 {%0,%1,%2,%3}, [%4];" \
        : "=r"(r0), "=r"(r1), "=r"(r2), "=r"(r3) : "r"(a))
#define LDSM_X4T(r0, r1, r2, r3, a) \
    asm volatile("ldmatrix.sync.aligned.m8n8.x4.trans.shared.b16 {%0,%1,%2,%3}, [%4];" \
        : "=r"(r0), "=r"(r1), "=r"(r2), "=r"(r3) : "r"(a))
#define MMA_BF16(d, a, b0, b1) \
    asm volatile("mma.sync.aligned.m16n8k16.row.col.f32.bf16.bf16.f32 " \
        "{%0,%1,%2,%3}, {%4,%5,%6,%7}, {%8,%9}, {%0,%1,%2,%3};" \
        : "+f"((d)[0]), "+f"((d)[1]), "+f"((d)[2]), "+f"((d)[3]) \
        : "r"((a)[0]), "r"((a)[1]), "r"((a)[2]), "r"((a)[3]), "r"(b0), "r"(b1))

__device__ __forceinline__ uint32_t packbf(float x, float y) {
    __nv_bfloat162 h = __floats2bfloat162_rn(x, y);
    return *(uint32_t*)&h;
}

// ---------------- class_ids dtype detection ----------------
__global__ void k_flag_init() { g_isI32 = 0; }
__global__ void k_flag_detect(const int* __restrict__ p) {
    int i = blockIdx.x * blockDim.x + threadIdx.x;
    if (i < 4096 && p[2 * i + 1] != 0) g_isI32 = 1;
}

// ---------------- conv1: 3 pixels per thread, 16 oc ----------------
__global__ void k_conv1(const float* __restrict__ img, const float* __restrict__ w,
                        const float* __restrict__ b, float* __restrict__ out) {
    __shared__ float ws[75 * 16];   // [k][oc]
    __shared__ float bs[16];
    for (int i = threadIdx.x; i < 1200; i += 256) {
        int oc = i / 75, k = i % 75;
        ws[k * 16 + oc] = w[i];
    }
    if (threadIdx.x < 16) bs[threadIdx.x] = b[threadIdx.x];
    __syncthreads();

    int idx = blockIdx.x * 256 + threadIdx.x;   // 8192*18*6 items
    int g  = idx % 6;
    int oy = (idx / 6) % H1;
    int n  = idx / (6 * H1);
    int ox0 = g * 3;
    const float* ip = img + (size_t)n * 4800;

    float acc[3][16];
    #pragma unroll
    for (int p = 0; p < 3; p++)
        #pragma unroll
        for (int oc = 0; oc < 16; oc++) acc[p][oc] = bs[oc];

    #pragma unroll
    for (int ic = 0; ic < 3; ic++) {
        #pragma unroll
        for (int ky = 0; ky < 5; ky++) {
            const float* row = ip + ic * 1600 + (2 * oy + ky) * 40 + ox0 * 2;
            float rv[9];
            #pragma unroll
            for (int x = 0; x < 9; x++) rv[x] = row[x];
            #pragma unroll
            for (int kx = 0; kx < 5; kx++) {
                const float4* wp = (const float4*)&ws[((ic * 5 + ky) * 5 + kx) * 16];
                float4 w0 = wp[0], w1 = wp[1], w2 = wp[2], w3 = wp[3];
                #pragma unroll
                for (int p = 0; p < 3; p++) {
                    float v = rv[2 * p + kx];
                    acc[p][0]  += v * w0.x; acc[p][1]  += v * w0.y; acc[p][2]  += v * w0.z; acc[p][3]  += v * w0.w;
                    acc[p][4]  += v * w1.x; acc[p][5]  += v * w1.y; acc[p][6]  += v * w1.z; acc[p][7]  += v * w1.w;
                    acc[p][8]  += v * w2.x; acc[p][9]  += v * w2.y; acc[p][10] += v * w2.z; acc[p][11] += v * w2.w;
                    acc[p][12] += v * w3.x; acc[p][13] += v * w3.y; acc[p][14] += v * w3.z; acc[p][15] += v * w3.w;
                }
            }
        }
    }
    float* op = out + (size_t)n * (16 * 324) + oy * H1 + ox0;
    #pragma unroll
    for (int oc = 0; oc < 16; oc++)
        #pragma unroll
        for (int p = 0; p < 3; p++)
            op[oc * 324 + p] = fmaxf(acc[p][oc], 0.f);
}

// ---------------- conv2: 4 pixels per thread, 32 oc ----------------
__global__ void k_conv2(const float* __restrict__ in, const float* __restrict__ w,
                        const float* __restrict__ b, float* __restrict__ out) {
    __shared__ float ws[144 * 32];  // [k][oc]
    __shared__ float bs[32];
    for (int i = threadIdx.x; i < 4608; i += 256) {
        int oc = i / 144, k = i % 144;
        ws[k * 32 + oc] = w[i];
    }
    if (threadIdx.x < 32) bs[threadIdx.x] = b[threadIdx.x];
    __syncthreads();

    int idx = blockIdx.x * 256 + threadIdx.x;   // 8192*8*2 items
    int g  = idx & 1;
    int oy = (idx >> 1) & 7;
    int n  = idx >> 4;
    int ox0 = g * 4;
    const float* ip = in + (size_t)n * (16 * 324);

    float acc[4][32];
    #pragma unroll
    for (int p = 0; p < 4; p++)
        #pragma unroll
        for (int oc = 0; oc < 32; oc++) acc[p][oc] = bs[oc];

    #pragma unroll 2
    for (int ic = 0; ic < 16; ic++) {
        #pragma unroll
        for (int ky = 0; ky < 3; ky++) {
            const float* row = ip + ic * 324 + (2 * oy + ky) * H1 + ox0 * 2;
            float rv[9];
            #pragma unroll
            for (int x = 0; x < 9; x++) rv[x] = row[x];
            #pragma unroll
            for (int kx = 0; kx < 3; kx++) {
                const float4* wp = (const float4*)&ws[(ic * 9 + ky * 3 + kx) * 32];
                #pragma unroll
                for (int q = 0; q < 8; q++) {
                    float4 wv = wp[q];
                    #pragma unroll
                    for (int p = 0; p < 4; p++) {
                        float v = rv[2 * p + kx];
                        acc[p][q * 4 + 0] += v * wv.x;
                        acc[p][q * 4 + 1] += v * wv.y;
                        acc[p][q * 4 + 2] += v * wv.z;
                        acc[p][q * 4 + 3] += v * wv.w;
                    }
                }
            }
        }
    }
    float* op = out + (size_t)n * FLAT + oy * H2 + ox0;
    #pragma unroll
    for (int oc = 0; oc < 32; oc++)
        #pragma unroll
        for (int p = 0; p < 4; p++)
            op[oc * 64 + p] = fmaxf(acc[p][oc], 0.f);
}

// ---------------- generic tiled SGEMM: C = act(A @ B^T + bias) ----------------
__global__ void k_gemm_abt(const float* __restrict__ A, int lda,
                           const float* __restrict__ B, int ldb,
                           const float* __restrict__ bias,
                           float* __restrict__ C, int ldc,
                           int K, int act) {
    __shared__ float As[16][68];
    __shared__ float Bs[16][68];
    int m0 = blockIdx.y * 64, n0 = blockIdx.x * 64;
    int tid = threadIdx.x;
    int tr = tid / 16, tc = tid % 16;
    int lrow = tid >> 2, lkg = (tid & 3) * 4;
    float acc[4][4] = {};
    for (int k0 = 0; k0 < K; k0 += 16) {
        float4 av = *(const float4*)(A + (size_t)(m0 + lrow) * lda + k0 + lkg);
        float4 bv = *(const float4*)(B + (size_t)(n0 + lrow) * ldb + k0 + lkg);
        As[lkg + 0][lrow] = av.x; As[lkg + 1][lrow] = av.y;
        As[lkg + 2][lrow] = av.z; As[lkg + 3][lrow] = av.w;
        Bs[lkg + 0][lrow] = bv.x; Bs[lkg + 1][lrow] = bv.y;
        Bs[lkg + 2][lrow] = bv.z; Bs[lkg + 3][lrow] = bv.w;
        __syncthreads();
        #pragma unroll
        for (int k = 0; k < 16; k++) {
            float4 a = *(const float4*)&As[k][tr * 4];
            float4 b = *(const float4*)&Bs[k][tc * 4];
            acc[0][0] += a.x * b.x; acc[0][1] += a.x * b.y; acc[0][2] += a.x * b.z; acc[0][3] += a.x * b.w;
            acc[1][0] += a.y * b.x; acc[1][1] += a.y * b.y; acc[1][2] += a.y * b.z; acc[1][3] += a.y * b.w;
            acc[2][0] += a.z * b.x; acc[2][1] += a.z * b.y; acc[2][2] += a.z * b.z; acc[2][3] += a.z * b.w;
            acc[3][0] += a.w * b.x; acc[3][1] += a.w * b.y; acc[3][2] += a.w * b.z; acc[3][3] += a.w * b.w;
        }
        __syncthreads();
    }
    #pragma unroll
    for (int i = 0; i < 4; i++) {
        int row = m0 + tr * 4 + i;
        #pragma unroll
        for (int j = 0; j < 4; j++) {
            int col = n0 + tc * 4 + j;
            float v = acc[i][j] + bias[col];
            if (act == 1) v = fmaxf(v, 0.f);
            C[(size_t)row * ldc + col] = v;
        }
    }
}

// ---------------- embedding ----------------
__global__ void k_embed(const int* __restrict__ cls, const float* __restrict__ table,
                        float* __restrict__ feat) {
    int idx = blockIdx.x * 256 + threadIdx.x;
    if (idx >= NB * 16) return;
    int i = idx >> 4, j = idx & 15;
    int id = g_isI32 ? cls[i] : cls[2 * i];
    feat[i * FEAT + 128 + j] = table[id * 16 + j];
}

// ---------------- GRU ----------------
__global__ void k_gru(const float* __restrict__ gi, const float* __restrict__ gh,
                      const float* __restrict__ h, float* __restrict__ nh) {
    int idx = blockIdx.x * 256 + threadIdx.x;
    if (idx >= NB * HD) return;
    int i = idx >> 7, j = idx & 127;
    const float* a = gi + i * G3H;
    const float* c = gh + i * G3H;
    float r = 1.f / (1.f + __expf(-(a[j] + c[j])));
    float z = 1.f / (1.f + __expf(-(a[128 + j] + c[128 + j])));
    float n = tanhf(a[256 + j] + r * c[256 + j]);
    nh[idx] = (1.f - z) * n + z * h[idx];
}

// ---------------- fp32 -> bf16 convert ----------------
__global__ void k_cvtbf(const float* __restrict__ X, __nv_bfloat16* __restrict__ Y) {
    int i = blockIdx.x * 256 + threadIdx.x;   // pairs
    float2 v = ((const float2*)X)[i];
    ((__nv_bfloat162*)Y)[i] = __floats2bfloat162_rn(v.x, v.y);
}

// ============ mma.sync bf16 flash attention (split-KV over 2 halves) ============
// grid 128: row0 = (bx&63)*128 Q rows; half = bx>>6 -> cols half*4096..+4096.
// 8 warps x 16 rows. Unnormalized: p = adj ? exp(s) : 0; O += P*V; l per row.
__global__ void __launch_bounds__(256, 1)
k_attn_mma(const float* __restrict__ Qf, const __nv_bfloat16* __restrict__ Kb,
           const __nv_bfloat16* __restrict__ Vb, const int* __restrict__ adj,
           float* __restrict__ Opart, float* __restrict__ lpart) {
    extern __shared__ char smem[];
    char* Ks = smem;            // 128 rows x 256B (swizzled)
    char* Vs = smem + 32768;
    uint32_t KsA = smem_u32(Ks);
    uint32_t VsA = smem_u32(Vs);

    int tid  = threadIdx.x;
    int wid  = tid >> 5;
    int lane = tid & 31;
    int m    = lane >> 3;       // ldmatrix quad group
    int row0 = (blockIdx.x & 63) * 128;
    int half = blockIdx.x >> 6;
    int cst  = half * 4096;
    const float scale = 0.08838834764831845f;   // 1/sqrt(128)

    // ---- stage Q (fp32 -> bf16, swizzled) into Ks, then ldmatrix into registers ----
    #pragma unroll
    for (int it = 0; it < 8; it++) {
        int id = tid + it * 256;          // 2048 units
        int r = id >> 4, u = id & 15;
        const float4* qp = (const float4*)(Qf + (size_t)(row0 + r) * 128 + u * 8);
        float4 v0 = qp[0], v1 = qp[1];
        uint32_t pk[4] = { packbf(v0.x, v0.y), packbf(v0.z, v0.w),
                           packbf(v1.x, v1.y), packbf(v1.z, v1.w) };
        *(int4*)(Ks + r * 256 + ((u ^ (r & 7)) * 16)) = *(int4*)pk;
    }
    __syncthreads();

    uint32_t qf[8][4];
    #pragma unroll
    for (int kk = 0; kk < 8; kk++) {
        int r = wid * 16 + (m & 1) * 8 + (lane & 7);
        int u = kk * 2 + (m >> 1);
        uint32_t a = KsA + r * 256 + ((u ^ (r & 7)) * 16);
        LDSM_X4(qf[kk][0], qf[kk][1], qf[kk][2], qf[kk][3], a);
    }
    __syncthreads();

    float oacc[16][4];
    #pragma unroll
    for (int j = 0; j < 16; j++)
        #pragma unroll
        for (int i = 0; i < 4; i++) oacc[j][i] = 0.f;
    float lsum0 = 0.f, lsum1 = 0.f;

    int grow0 = row0 + wid * 16 + (lane >> 2);
    const int* adjr0 = adj + (size_t)grow0 * NB;
    const int* adjr1 = adjr0 + (size_t)8 * NB;

    for (int t = 0; t < 32; t++) {
        int c0 = cst + t * 128;
        // ---- load K/V tiles (bf16, swizzled) ----
        #pragma unroll
        for (int it = 0; it < 8; it++) {
            int id = tid + it * 256;
            int r = id >> 4, u = id & 15;
            int4 kv = *(const int4*)(Kb + (size_t)(c0 + r) * 128 + u * 8);
            int4 vv = *(const int4*)(Vb + (size_t)(c0 + r) * 128 + u * 8);
            int off = r * 256 + ((u ^ (r & 7)) * 16);
            *(int4*)(Ks + off) = kv;
            *(int4*)(Vs + off) = vv;
        }
        __syncthreads();

        // ---- S = Q * K^T : sacc[16 n-tiles][4] ----
        float sacc[16][4];
        #pragma unroll
        for (int j = 0; j < 16; j++)
            #pragma unroll
            for (int i = 0; i < 4; i++) sacc[j][i] = 0.f;

        #pragma unroll
        for (int kk = 0; kk < 8; kk++) {
            #pragma unroll
            for (int jp = 0; jp < 8; jp++) {
                int nr = jp * 16 + (m >> 1) * 8 + (lane & 7);
                int u  = kk * 2 + (m & 1);
                uint32_t a = KsA + nr * 256 + ((u ^ (nr & 7)) * 16);
                uint32_t b0, b1, b2, b3;
                LDSM_X4(b0, b1, b2, b3, a);
                MMA_BF16(sacc[2 * jp],     qf[kk], b0, b1);
                MMA_BF16(sacc[2 * jp + 1], qf[kk], b2, b3);
            }
        }

        // ---- mask + exp + pack P into A-fragments ----
        uint32_t pf[8][4];
        int cb = c0 + (lane & 3) * 2;
        #pragma unroll
        for (int s = 0; s < 8; s++) {
            int ca = cb + s * 16;       // tile 2s cols
            int cbb = ca + 8;           // tile 2s+1 cols
            int2 m00 = *(const int2*)(adjr0 + ca);
            int2 m01 = *(const int2*)(adjr1 + ca);
            int2 m10 = *(const int2*)(adjr0 + cbb);
            int2 m11 = *(const int2*)(adjr1 + cbb);
            float p00 = m00.x ? __expf(sacc[2 * s][0] * scale) : 0.f;
            float p01 = m00.y ? __expf(sacc[2 * s][1] * scale) : 0.f;
            float p02 = m01.x ? __expf(sacc[2 * s][2] * scale) : 0.f;
            float p03 = m01.y ? __expf(sacc[2 * s][3] * scale) : 0.f;
            float p10 = m10.x ? __expf(sacc[2 * s + 1][0] * scale) : 0.f;
            float p11 = m10.y ? __expf(sacc[2 * s + 1][1] * scale) : 0.f;
            float p12 = m11.x ? __expf(sacc[2 * s + 1][2] * scale) : 0.f;
            float p13 = m11.y ? __expf(sacc[2 * s + 1][3] * scale) : 0.f;
            lsum0 += (p00 + p01) + (p10 + p11);
            lsum1 += (p02 + p03) + (p12 + p13);
            pf[s][0] = packbf(p00, p01);
            pf[s][1] = packbf(p02, p03);
            pf[s][2] = packbf(p10, p11);
            pf[s][3] = packbf(p12, p13);
        }

        // ---- O += P * V ----
        #pragma unroll
        for (int sp = 0; sp < 4; sp++) {
            #pragma unroll
            for (int jj = 0; jj < 16; jj++) {
                int cr = sp * 32 + m * 8 + (lane & 7);
                uint32_t a = VsA + cr * 256 + ((jj ^ (cr & 7)) * 16);
                uint32_t b0, b1, b2, b3;
                LDSM_X4T(b0, b1, b2, b3, a);
                MMA_BF16(oacc[jj], pf[2 * sp],     b0, b1);
                MMA_BF16(oacc[jj], pf[2 * sp + 1], b2, b3);
            }
        }
        __syncthreads();
    }

    // ---- row-sum reduce + write ----
    lsum0 += __shfl_xor_sync(0xffffffffu, lsum0, 1);
    lsum0 += __shfl_xor_sync(0xffffffffu, lsum0, 2);
    lsum1 += __shfl_xor_sync(0xffffffffu, lsum1, 1);
    lsum1 += __shfl_xor_sync(0xffffffffu, lsum1, 2);
    if ((lane & 3) == 0) {
        lpart[half * NB + grow0]     = lsum0;
        lpart[half * NB + grow0 + 8] = lsum1;
    }
    float* o0 = Opart + ((size_t)half * NB + grow0) * 128 + (lane & 3) * 2;
    float* o1 = o0 + (size_t)8 * 128;
    #pragma unroll
    for (int jj = 0; jj < 16; jj++) {
        *(float2*)(o0 + jj * 8) = make_float2(oacc[jj][0], oacc[jj][1]);
        *(float2*)(o1 + jj * 8) = make_float2(oacc[jj][2], oacc[jj][3]);
    }
}

// ---------------- merge split-KV halves ----------------
__global__ void k_merge(const float* __restrict__ O, const float* __restrict__ l,
                        float* __restrict__ ctx) {
    int idx = blockIdx.x * 256 + threadIdx.x;   // NB*HD
    int r = idx >> 7;
    float denom = l[r] + l[NB + r];
    ctx[idx] = (O[idx] + O[NB * HD + idx]) / denom;
}

// ---------------- final head ----------------
__global__ void k_fcq(const float* __restrict__ nh, const float* __restrict__ sw,
                      const float* __restrict__ W, const float* __restrict__ b,
                      float* __restrict__ q) {
    int idx = blockIdx.x * 256 + threadIdx.x;
    if (idx >= NB * 5) return;
    int i = idx / 5, a = idx % 5;
    const float* w = W + a * 256;
    const float* hr = nh + i * 128;
    const float* sr = sw + i * 128;
    float s = b[a];
    #pragma unroll 8
    for (int k = 0; k < 128; k++) s += hr[k] * w[k];
    #pragma unroll 8
    for (int k = 0; k < 128; k++) s += sr[k] * w[128 + k];
    q[idx] = s;
}

// ---------------- launch ----------------
extern "C" void kernel_launch(void* const* d_in, const int* in_sizes, int n_in,
                              void* d_out, int out_size) {
    const float* img = (const float*)d_in[0];
    const int*   adj = (const int*)  d_in[1];
    const int*   cls = (const int*)  d_in[2];
    const float* h0  = (const float*)d_in[3];
    const float* c1w = (const float*)d_in[4];
    const float* c1b = (const float*)d_in[5];
    const float* c2w = (const float*)d_in[6];
    const float* c2b = (const float*)d_in[7];
    const float* fvw = (const float*)d_in[8];
    const float* fvb = (const float*)d_in[9];
    const float* emb = (const float*)d_in[10];
    const float* wih = (const float*)d_in[11];
    const float* whh = (const float*)d_in[12];
    const float* bih = (const float*)d_in[13];
    const float* bhh = (const float*)d_in[14];
    const float* wqw = (const float*)d_in[15];
    const float* wqb = (const float*)d_in[16];
    const float* wkw = (const float*)d_in[17];
    const float* wkb = (const float*)d_in[18];
    const float* wvw = (const float*)d_in[19];
    const float* wvb = (const float*)d_in[20];
    const float* aow = (const float*)d_in[21];
    const float* aob = (const float*)d_in[22];
    const float* fqw = (const float*)d_in[23];
    const float* fqb = (const float*)d_in[24];

    float* qout = (float*)d_out;
    float* nh   = qout + NB * 5;

    float *pc1, *pflat, *pfeat, *pgi, *pgh, *pQ, *pK, *pV, *pctx, *pswarm, *pOp, *plp;
    __nv_bfloat16 *pKb, *pVb;
    cudaGetSymbolAddress((void**)&pc1,    g_conv1);
    cudaGetSymbolAddress((void**)&pflat,  g_flat);
    cudaGetSymbolAddress((void**)&pfeat,  g_feat);
    cudaGetSymbolAddress((void**)&pgi,    g_gi);
    cudaGetSymbolAddress((void**)&pgh,    g_gh);
    cudaGetSymbolAddress((void**)&pQ,     g_Q);
    cudaGetSymbolAddress((void**)&pK,     g_K);
    cudaGetSymbolAddress((void**)&pV,     g_V);
    cudaGetSymbolAddress((void**)&pctx,   g_ctx);
    cudaGetSymbolAddress((void**)&pswarm, g_swarm);
    cudaGetSymbolAddress((void**)&pKb,    g_Kb);
    cudaGetSymbolAddress((void**)&pVb,    g_Vb);
    cudaGetSymbolAddress((void**)&pOp,    g_Opart);
    cudaGetSymbolAddress((void**)&plp,    g_lpart);

    k_flag_init<<<1, 1>>>();
    k_flag_detect<<<16, 256>>>(cls);

    // CNN encoder
    k_conv1<<<(NB * H1 * 6) / 256, 256>>>(img, c1w, c1b, pc1);
    k_conv2<<<(NB * H2 * 2) / 256, 256>>>(pc1, c2w, c2b, pflat);

    { dim3 g(128 / 64, NB / 64); k_gemm_abt<<<g, 256>>>(pflat, FLAT, fvw, FLAT, fvb, pfeat, FEAT, FLAT, 1); }
    k_embed<<<(NB * 16) / 256, 256>>>(cls, emb, pfeat);

    // GRU
    { dim3 g(G3H / 64, NB / 64); k_gemm_abt<<<g, 256>>>(pfeat, FEAT, wih, FEAT, bih, pgi, G3H, FEAT, 0); }
    { dim3 g(G3H / 64, NB / 64); k_gemm_abt<<<g, 256>>>(h0,    HD,   whh, HD,   bhh, pgh, G3H, HD,   0); }
    k_gru<<<(NB * HD) / 256, 256>>>(pgi, pgh, h0, nh);

    // Q, K, V projections (fp32)
    { dim3 g(HD / 64, NB / 64); k_gemm_abt<<<g, 256>>>(nh, HD, wqw, HD, wqb, pQ, HD, HD, 0); }
    { dim3 g(HD / 64, NB / 64); k_gemm_abt<<<g, 256>>>(nh, HD, wkw, HD, wkb, pK, HD, HD, 0); }
    { dim3 g(HD / 64, NB / 64); k_gemm_abt<<<g, 256>>>(nh, HD, wvw, HD, wvb, pV, HD, HD, 0); }

    // bf16 prep
    k_cvtbf<<<(NB * HD / 2) / 256, 256>>>(pK, pKb);
    k_cvtbf<<<(NB * HD / 2) / 256, 256>>>(pV, pVb);

    // mma.sync flash attention
    const int attn_smem = 65536;
    cudaFuncSetAttribute(k_attn_mma, cudaFuncAttributeMaxDynamicSharedMemorySize, attn_smem);
    k_attn_mma<<<128, 256, attn_smem>>>(pQ, pKb, pVb, adj, pOp, plp);
    k_merge<<<(NB * HD) / 256, 256>>>(pOp, plp, pctx);

    // attention output projection
    { dim3 g(HD / 64, NB / 64); k_gemm_abt<<<g, 256>>>(pctx, HD, aow, HD, aob, pswarm, HD, HD, 0); }

    k_fcq<<<(NB * 5 + 255) / 256, 256>>>(nh, pswarm, fqw, fqb, qout);
}

// round 8
// speedup vs baseline: 5.7913x; 1.0821x over previous
#include <cuda_runtime.h>
#include <cuda_bf16.h>
#include <cstdint>
#include <math.h>

// ---------------- problem dims ----------------
#define NB    8192
#define HD    128
#define H1    18
#define H2    8
#define FLAT  2048
#define FEAT  144
#define G3H   384

// ---------------- scratch ----------------
__device__ float g_conv1[NB * 16 * H1 * H1];
__device__ float g_flat [NB * FLAT];
__device__ float g_feat [NB * FEAT];
__device__ float g_gi   [NB * G3H];
__device__ float g_gh   [NB * G3H];
__device__ float g_Q    [NB * HD];
__device__ float g_K    [NB * HD];
__device__ float g_V    [NB * HD];
__device__ float g_ctx  [NB * HD];
__device__ float g_swarm[NB * HD];
__device__ __nv_bfloat16 g_Kb[NB * HD];
__device__ __nv_bfloat16 g_Vb[NB * HD];
__device__ float g_Opart[2 * NB * HD];
__device__ float g_lpart[2 * NB];
__device__ int   g_isI32;

// ---------------- mma/ldmatrix helpers (base ISA, legal on sm_103) ----------------
__device__ __forceinline__ uint32_t smem_u32(const void* p) {
    uint32_t a;
    asm("{ .reg .u64 t; cvta.to.shared.u64 t, %1; cvt.u32.u64 %0, t; }" : "=r"(a) : "l"(p));
    return a;
}
#define LDSM_X4(r0, r1, r2, r3, a) \
    asm volatile("ldmatrix.sync.aligned.m8n8.x4.shared.b16 {%0,%1,%2,%3}, [%4];" \
        : "=r"(r0), "=r"(r1), "=r"(r2), "=r"(r3) : "r"(a))
#define LDSM_X4T(r0, r1, r2, r3, a) \
    asm volatile("ldmatrix.sync.aligned.m8n8.x4.trans.shared.b16 {%0,%1,%2,%3}, [%4];" \
        : "=r"(r0), "=r"(r1), "=r"(r2), "=r"(r3) : "r"(a))
#define MMA_BF16(d, a, b0, b1) \
    asm volatile("mma.sync.aligned.m16n8k16.row.col.f32.bf16.bf16.f32 " \
        "{%0,%1,%2,%3}, {%4,%5,%6,%7}, {%8,%9}, {%0,%1,%2,%3};" \
        : "+f"((d)[0]), "+f"((d)[1]), "+f"((d)[2]), "+f"((d)[3]) \
        : "r"((a)[0]), "r"((a)[1]), "r"((a)[2]), "r"((a)[3]), "r"(b0), "r"(b1))

__device__ __forceinline__ uint32_t packbf(float x, float y) {
    __nv_bfloat162 h = __floats2bfloat162_rn(x, y);
    return *(uint32_t*)&h;
}

// ---------------- class_ids dtype detection ----------------
__global__ void k_flag_init() { g_isI32 = 0; }
__global__ void k_flag_detect(const int* __restrict__ p) {
    int i = blockIdx.x * blockDim.x + threadIdx.x;
    if (i < 4096 && p[2 * i + 1] != 0) g_isI32 = 1;
}

// ---------------- conv1: 3 pixels per thread, 16 oc ----------------
__global__ void k_conv1(const float* __restrict__ img, const float* __restrict__ w,
                        const float* __restrict__ b, float* __restrict__ out) {
    __shared__ float ws[75 * 16];   // [k][oc]
    __shared__ float bs[16];
    for (int i = threadIdx.x; i < 1200; i += 256) {
        int oc = i / 75, k = i % 75;
        ws[k * 16 + oc] = w[i];
    }
    if (threadIdx.x < 16) bs[threadIdx.x] = b[threadIdx.x];
    __syncthreads();

    int idx = blockIdx.x * 256 + threadIdx.x;   // 8192*18*6 items
    int g  = idx % 6;
    int oy = (idx / 6) % H1;
    int n  = idx / (6 * H1);
    int ox0 = g * 3;
    const float* ip = img + (size_t)n * 4800;

    float acc[3][16];
    #pragma unroll
    for (int p = 0; p < 3; p++)
        #pragma unroll
        for (int oc = 0; oc < 16; oc++) acc[p][oc] = bs[oc];

    #pragma unroll
    for (int ic = 0; ic < 3; ic++) {
        #pragma unroll
        for (int ky = 0; ky < 5; ky++) {
            const float* row = ip + ic * 1600 + (2 * oy + ky) * 40 + ox0 * 2;
            float rv[9];
            #pragma unroll
            for (int x = 0; x < 9; x++) rv[x] = row[x];
            #pragma unroll
            for (int kx = 0; kx < 5; kx++) {
                const float4* wp = (const float4*)&ws[((ic * 5 + ky) * 5 + kx) * 16];
                float4 w0 = wp[0], w1 = wp[1], w2 = wp[2], w3 = wp[3];
                #pragma unroll
                for (int p = 0; p < 3; p++) {
                    float v = rv[2 * p + kx];
                    acc[p][0]  += v * w0.x; acc[p][1]  += v * w0.y; acc[p][2]  += v * w0.z; acc[p][3]  += v * w0.w;
                    acc[p][4]  += v * w1.x; acc[p][5]  += v * w1.y; acc[p][6]  += v * w1.z; acc[p][7]  += v * w1.w;
                    acc[p][8]  += v * w2.x; acc[p][9]  += v * w2.y; acc[p][10] += v * w2.z; acc[p][11] += v * w2.w;
                    acc[p][12] += v * w3.x; acc[p][13] += v * w3.y; acc[p][14] += v * w3.z; acc[p][15] += v * w3.w;
                }
            }
        }
    }
    float* op = out + (size_t)n * (16 * 324) + oy * H1 + ox0;
    #pragma unroll
    for (int oc = 0; oc < 16; oc++)
        #pragma unroll
        for (int p = 0; p < 3; p++)
            op[oc * 324 + p] = fmaxf(acc[p][oc], 0.f);
}

// ---------------- conv2: 2 pixels per thread, 32 oc, 2 CTAs/SM ----------------
__global__ void __launch_bounds__(256, 2)
k_conv2(const float* __restrict__ in, const float* __restrict__ w,
        const float* __restrict__ b, float* __restrict__ out) {
    __shared__ float ws[144 * 32];  // [k][oc]
    __shared__ float bs[32];
    for (int i = threadIdx.x; i < 4608; i += 256) {
        int oc = i / 144, k = i % 144;
        ws[k * 32 + oc] = w[i];
    }
    if (threadIdx.x < 32) bs[threadIdx.x] = b[threadIdx.x];
    __syncthreads();

    int idx = blockIdx.x * 256 + threadIdx.x;   // 8192*8*4 items
    int g  = idx & 3;                           // 2-pixel group
    int oy = (idx >> 2) & 7;
    int n  = idx >> 5;
    int ox0 = g * 2;
    const float* ip = in + (size_t)n * (16 * 324);

    float acc[2][32];
    #pragma unroll
    for (int p = 0; p < 2; p++)
        #pragma unroll
        for (int oc = 0; oc < 32; oc++) acc[p][oc] = bs[oc];

    #pragma unroll 2
    for (int ic = 0; ic < 16; ic++) {
        #pragma unroll
        for (int ky = 0; ky < 3; ky++) {
            const float* row = ip + ic * 324 + (2 * oy + ky) * H1 + ox0 * 2;
            float rv[5];
            #pragma unroll
            for (int x = 0; x < 5; x++) rv[x] = row[x];
            #pragma unroll
            for (int kx = 0; kx < 3; kx++) {
                const float4* wp = (const float4*)&ws[(ic * 9 + ky * 3 + kx) * 32];
                #pragma unroll
                for (int q = 0; q < 8; q++) {
                    float4 wv = wp[q];
                    #pragma unroll
                    for (int p = 0; p < 2; p++) {
                        float v = rv[2 * p + kx];
                        acc[p][q * 4 + 0] += v * wv.x;
                        acc[p][q * 4 + 1] += v * wv.y;
                        acc[p][q * 4 + 2] += v * wv.z;
                        acc[p][q * 4 + 3] += v * wv.w;
                    }
                }
            }
        }
    }
    float* op = out + (size_t)n * FLAT + oy * H2 + ox0;
    #pragma unroll
    for (int oc = 0; oc < 32; oc++)
        #pragma unroll
        for (int p = 0; p < 2; p++)
            op[oc * 64 + p] = fmaxf(acc[p][oc], 0.f);
}

// ------- fp32 SGEMM: C[M,N] = act(A[M,K] @ B[N,K]^T + bias), 128x64 tile, BK=16 -------
// 256 threads, microtile 8x4 (rows tr*4+{0..3} and +64; cols tc*4). M%128==0, N%64==0, K%16==0.
__global__ void __launch_bounds__(256, 2)
k_gemm128(const float* __restrict__ A, int lda,
          const float* __restrict__ B, int ldb,
          const float* __restrict__ bias,
          float* __restrict__ C, int ldc,
          int K, int act) {
    __shared__ float As[16][132];
    __shared__ float Bs[16][68];
    int m0 = blockIdx.y * 128, n0 = blockIdx.x * 64;
    int tid = threadIdx.x;
    int ra = tid >> 1, ka = (tid & 1) * 8;     // A: 128 rows x 16 k, 2 float4/thread
    int rb = tid >> 2, kb = (tid & 3) * 4;     // B: 64 rows x 16 k, 1 float4/thread
    int tr = tid >> 4, tc = tid & 15;

    float acc[8][4];
    #pragma unroll
    for (int i = 0; i < 8; i++)
        #pragma unroll
        for (int j = 0; j < 4; j++) acc[i][j] = 0.f;

    const float* Ap = A + (size_t)(m0 + ra) * lda + ka;
    const float* Bp = B + (size_t)(n0 + rb) * ldb + kb;

    for (int k0 = 0; k0 < K; k0 += 16) {
        float4 a0 = *(const float4*)(Ap + k0);
        float4 a1 = *(const float4*)(Ap + k0 + 4);
        float4 bv = *(const float4*)(Bp + k0);
        As[ka + 0][ra] = a0.x; As[ka + 1][ra] = a0.y; As[ka + 2][ra] = a0.z; As[ka + 3][ra] = a0.w;
        As[ka + 4][ra] = a1.x; As[ka + 5][ra] = a1.y; As[ka + 6][ra] = a1.z; As[ka + 7][ra] = a1.w;
        Bs[kb + 0][rb] = bv.x; Bs[kb + 1][rb] = bv.y; Bs[kb + 2][rb] = bv.z; Bs[kb + 3][rb] = bv.w;
        __syncthreads();
        #pragma unroll
        for (int k = 0; k < 16; k++) {
            float4 x0 = *(const float4*)&As[k][tr * 4];
            float4 x1 = *(const float4*)&As[k][tr * 4 + 64];
            float4 y  = *(const float4*)&Bs[k][tc * 4];
            acc[0][0] += x0.x * y.x; acc[0][1] += x0.x * y.y; acc[0][2] += x0.x * y.z; acc[0][3] += x0.x * y.w;
            acc[1][0] += x0.y * y.x; acc[1][1] += x0.y * y.y; acc[1][2] += x0.y * y.z; acc[1][3] += x0.y * y.w;
            acc[2][0] += x0.z * y.x; acc[2][1] += x0.z * y.y; acc[2][2] += x0.z * y.z; acc[2][3] += x0.z * y.w;
            acc[3][0] += x0.w * y.x; acc[3][1] += x0.w * y.y; acc[3][2] += x0.w * y.z; acc[3][3] += x0.w * y.w;
            acc[4][0] += x1.x * y.x; acc[4][1] += x1.x * y.y; acc[4][2] += x1.x * y.z; acc[4][3] += x1.x * y.w;
            acc[5][0] += x1.y * y.x; acc[5][1] += x1.y * y.y; acc[5][2] += x1.y * y.z; acc[5][3] += x1.y * y.w;
            acc[6][0] += x1.z * y.x; acc[6][1] += x1.z * y.y; acc[6][2] += x1.z * y.z; acc[6][3] += x1.z * y.w;
            acc[7][0] += x1.w * y.x; acc[7][1] += x1.w * y.y; acc[7][2] += x1.w * y.z; acc[7][3] += x1.w * y.w;
        }
        __syncthreads();
    }

    float bb[4];
    #pragma unroll
    for (int j = 0; j < 4; j++) bb[j] = bias[n0 + tc * 4 + j];
    #pragma unroll
    for (int i = 0; i < 8; i++) {
        int row = m0 + tr * 4 + (i & 3) + (i >> 2) * 64;
        float4 o;
        o.x = acc[i][0] + bb[0]; o.y = acc[i][1] + bb[1];
        o.z = acc[i][2] + bb[2]; o.w = acc[i][3] + bb[3];
        if (act == 1) {
            o.x = fmaxf(o.x, 0.f); o.y = fmaxf(o.y, 0.f);
            o.z = fmaxf(o.z, 0.f); o.w = fmaxf(o.w, 0.f);
        }
        *(float4*)(C + (size_t)row * ldc + n0 + tc * 4) = o;
    }
}

// ---------------- embedding ----------------
__global__ void k_embed(const int* __restrict__ cls, const float* __restrict__ table,
                        float* __restrict__ feat) {
    int idx = blockIdx.x * 256 + threadIdx.x;
    if (idx >= NB * 16) return;
    int i = idx >> 4, j = idx & 15;
    int id = g_isI32 ? cls[i] : cls[2 * i];
    feat[i * FEAT + 128 + j] = table[id * 16 + j];
}

// ---------------- GRU ----------------
__global__ void k_gru(const float* __restrict__ gi, const float* __restrict__ gh,
                      const float* __restrict__ h, float* __restrict__ nh) {
    int idx = blockIdx.x * 256 + threadIdx.x;
    if (idx >= NB * HD) return;
    int i = idx >> 7, j = idx & 127;
    const float* a = gi + i * G3H;
    const float* c = gh + i * G3H;
    float r = 1.f / (1.f + __expf(-(a[j] + c[j])));
    float z = 1.f / (1.f + __expf(-(a[128 + j] + c[128 + j])));
    float n = tanhf(a[256 + j] + r * c[256 + j]);
    nh[idx] = (1.f - z) * n + z * h[idx];
}

// ---------------- fp32 -> bf16 convert ----------------
__global__ void k_cvtbf(const float* __restrict__ X, __nv_bfloat16* __restrict__ Y) {
    int i = blockIdx.x * 256 + threadIdx.x;   // pairs
    float2 v = ((const float2*)X)[i];
    ((__nv_bfloat162*)Y)[i] = __floats2bfloat162_rn(v.x, v.y);
}

// ============ mma.sync bf16 flash attention (split-KV over 2 halves) ============
__global__ void __launch_bounds__(256, 1)
k_attn_mma(const float* __restrict__ Qf, const __nv_bfloat16* __restrict__ Kb,
           const __nv_bfloat16* __restrict__ Vb, const int* __restrict__ adj,
           float* __restrict__ Opart, float* __restrict__ lpart) {
    extern __shared__ char smem[];
    char* Ks = smem;            // 128 rows x 256B (swizzled)
    char* Vs = smem + 32768;
    uint32_t KsA = smem_u32(Ks);
    uint32_t VsA = smem_u32(Vs);

    int tid  = threadIdx.x;
    int wid  = tid >> 5;
    int lane = tid & 31;
    int m    = lane >> 3;
    int row0 = (blockIdx.x & 63) * 128;
    int half = blockIdx.x >> 6;
    int cst  = half * 4096;
    const float scale = 0.08838834764831845f;

    #pragma unroll
    for (int it = 0; it < 8; it++) {
        int id = tid + it * 256;
        int r = id >> 4, u = id & 15;
        const float4* qp = (const float4*)(Qf + (size_t)(row0 + r) * 128 + u * 8);
        float4 v0 = qp[0], v1 = qp[1];
        uint32_t pk[4] = { packbf(v0.x, v0.y), packbf(v0.z, v0.w),
                           packbf(v1.x, v1.y), packbf(v1.z, v1.w) };
        *(int4*)(Ks + r * 256 + ((u ^ (r & 7)) * 16)) = *(int4*)pk;
    }
    __syncthreads();

    uint32_t qf[8][4];
    #pragma unroll
    for (int kk = 0; kk < 8; kk++) {
        int r = wid * 16 + (m & 1) * 8 + (lane & 7);
        int u = kk * 2 + (m >> 1);
        uint32_t a = KsA + r * 256 + ((u ^ (r & 7)) * 16);
        LDSM_X4(qf[kk][0], qf[kk][1], qf[kk][2], qf[kk][3], a);
    }
    __syncthreads();

    float oacc[16][4];
    #pragma unroll
    for (int j = 0; j < 16; j++)
        #pragma unroll
        for (int i = 0; i < 4; i++) oacc[j][i] = 0.f;
    float lsum0 = 0.f, lsum1 = 0.f;

    int grow0 = row0 + wid * 16 + (lane >> 2);
    const int* adjr0 = adj + (size_t)grow0 * NB;
    const int* adjr1 = adjr0 + (size_t)8 * NB;

    for (int t = 0; t < 32; t++) {
        int c0 = cst + t * 128;
        #pragma unroll
        for (int it = 0; it < 8; it++) {
            int id = tid + it * 256;
            int r = id >> 4, u = id & 15;
            int4 kv = *(const int4*)(Kb + (size_t)(c0 + r) * 128 + u * 8);
            int4 vv = *(const int4*)(Vb + (size_t)(c0 + r) * 128 + u * 8);
            int off = r * 256 + ((u ^ (r & 7)) * 16);
            *(int4*)(Ks + off) = kv;
            *(int4*)(Vs + off) = vv;
        }
        __syncthreads();

        float sacc[16][4];
        #pragma unroll
        for (int j = 0; j < 16; j++)
            #pragma unroll
            for (int i = 0; i < 4; i++) sacc[j][i] = 0.f;

        #pragma unroll
        for (int kk = 0; kk < 8; kk++) {
            #pragma unroll
            for (int jp = 0; jp < 8; jp++) {
                int nr = jp * 16 + (m >> 1) * 8 + (lane & 7);
                int u  = kk * 2 + (m & 1);
                uint32_t a = KsA + nr * 256 + ((u ^ (nr & 7)) * 16);
                uint32_t b0, b1, b2, b3;
                LDSM_X4(b0, b1, b2, b3, a);
                MMA_BF16(sacc[2 * jp],     qf[kk], b0, b1);
                MMA_BF16(sacc[2 * jp + 1], qf[kk], b2, b3);
            }
        }

        uint32_t pf[8][4];
        int cb = c0 + (lane & 3) * 2;
        #pragma unroll
        for (int s = 0; s < 8; s++) {
            int ca = cb + s * 16;
            int cbb = ca + 8;
            int2 m00 = *(const int2*)(adjr0 + ca);
            int2 m01 = *(const int2*)(adjr1 + ca);
            int2 m10 = *(const int2*)(adjr0 + cbb);
            int2 m11 = *(const int2*)(adjr1 + cbb);
            float p00 = m00.x ? __expf(sacc[2 * s][0] * scale) : 0.f;
            float p01 = m00.y ? __expf(sacc[2 * s][1] * scale) : 0.f;
            float p02 = m01.x ? __expf(sacc[2 * s][2] * scale) : 0.f;
            float p03 = m01.y ? __expf(sacc[2 * s][3] * scale) : 0.f;
            float p10 = m10.x ? __expf(sacc[2 * s + 1][0] * scale) : 0.f;
            float p11 = m10.y ? __expf(sacc[2 * s + 1][1] * scale) : 0.f;
            float p12 = m11.x ? __expf(sacc[2 * s + 1][2] * scale) : 0.f;
            float p13 = m11.y ? __expf(sacc[2 * s + 1][3] * scale) : 0.f;
            lsum0 += (p00 + p01) + (p10 + p11);
            lsum1 += (p02 + p03) + (p12 + p13);
            pf[s][0] = packbf(p00, p01);
            pf[s][1] = packbf(p02, p03);
            pf[s][2] = packbf(p10, p11);
            pf[s][3] = packbf(p12, p13);
        }

        #pragma unroll
        for (int sp = 0; sp < 4; sp++) {
            #pragma unroll
            for (int jj = 0; jj < 16; jj++) {
                int cr = sp * 32 + m * 8 + (lane & 7);
                uint32_t a = VsA + cr * 256 + ((jj ^ (cr & 7)) * 16);
                uint32_t b0, b1, b2, b3;
                LDSM_X4T(b0, b1, b2, b3, a);
                MMA_BF16(oacc[jj], pf[2 * sp],     b0, b1);
                MMA_BF16(oacc[jj], pf[2 * sp + 1], b2, b3);
            }
        }
        __syncthreads();
    }

    lsum0 += __shfl_xor_sync(0xffffffffu, lsum0, 1);
    lsum0 += __shfl_xor_sync(0xffffffffu, lsum0, 2);
    lsum1 += __shfl_xor_sync(0xffffffffu, lsum1, 1);
    lsum1 += __shfl_xor_sync(0xffffffffu, lsum1, 2);
    if ((lane & 3) == 0) {
        lpart[half * NB + grow0]     = lsum0;
        lpart[half * NB + grow0 + 8] = lsum1;
    }
    float* o0 = Opart + ((size_t)half * NB + grow0) * 128 + (lane & 3) * 2;
    float* o1 = o0 + (size_t)8 * 128;
    #pragma unroll
    for (int jj = 0; jj < 16; jj++) {
        *(float2*)(o0 + jj * 8) = make_float2(oacc[jj][0], oacc[jj][1]);
        *(float2*)(o1 + jj * 8) = make_float2(oacc[jj][2], oacc[jj][3]);
    }
}

// ---------------- merge split-KV halves ----------------
__global__ void k_merge(const float* __restrict__ O, const float* __restrict__ l,
                        float* __restrict__ ctx) {
    int idx = blockIdx.x * 256 + threadIdx.x;
    int r = idx >> 7;
    float denom = l[r] + l[NB + r];
    ctx[idx] = (O[idx] + O[NB * HD + idx]) / denom;
}

// ---------------- final head ----------------
__global__ void k_fcq(const float* __restrict__ nh, const float* __restrict__ sw,
                      const float* __restrict__ W, const float* __restrict__ b,
                      float* __restrict__ q) {
    int idx = blockIdx.x * 256 + threadIdx.x;
    if (idx >= NB * 5) return;
    int i = idx / 5, a = idx % 5;
    const float* w = W + a * 256;
    const float* hr = nh + i * 128;
    const float* sr = sw + i * 128;
    float s = b[a];
    #pragma unroll 8
    for (int k = 0; k < 128; k++) s += hr[k] * w[k];
    #pragma unroll 8
    for (int k = 0; k < 128; k++) s += sr[k] * w[128 + k];
    q[idx] = s;
}

// ---------------- launch ----------------
extern "C" void kernel_launch(void* const* d_in, const int* in_sizes, int n_in,
                              void* d_out, int out_size) {
    const float* img = (const float*)d_in[0];
    const int*   adj = (const int*)  d_in[1];
    const int*   cls = (const int*)  d_in[2];
    const float* h0  = (const float*)d_in[3];
    const float* c1w = (const float*)d_in[4];
    const float* c1b = (const float*)d_in[5];
    const float* c2w = (const float*)d_in[6];
    const float* c2b = (const float*)d_in[7];
    const float* fvw = (const float*)d_in[8];
    const float* fvb = (const float*)d_in[9];
    const float* emb = (const float*)d_in[10];
    const float* wih = (const float*)d_in[11];
    const float* whh = (const float*)d_in[12];
    const float* bih = (const float*)d_in[13];
    const float* bhh = (const float*)d_in[14];
    const float* wqw = (const float*)d_in[15];
    const float* wqb = (const float*)d_in[16];
    const float* wkw = (const float*)d_in[17];
    const float* wkb = (const float*)d_in[18];
    const float* wvw = (const float*)d_in[19];
    const float* wvb = (const float*)d_in[20];
    const float* aow = (const float*)d_in[21];
    const float* aob = (const float*)d_in[22];
    const float* fqw = (const float*)d_in[23];
    const float* fqb = (const float*)d_in[24];

    float* qout = (float*)d_out;
    float* nh   = qout + NB * 5;

    float *pc1, *pflat, *pfeat, *pgi, *pgh, *pQ, *pK, *pV, *pctx, *pswarm, *pOp, *plp;
    __nv_bfloat16 *pKb, *pVb;
    cudaGetSymbolAddress((void**)&pc1,    g_conv1);
    cudaGetSymbolAddress((void**)&pflat,  g_flat);
    cudaGetSymbolAddress((void**)&pfeat,  g_feat);
    cudaGetSymbolAddress((void**)&pgi,    g_gi);
    cudaGetSymbolAddress((void**)&pgh,    g_gh);
    cudaGetSymbolAddress((void**)&pQ,     g_Q);
    cudaGetSymbolAddress((void**)&pK,     g_K);
    cudaGetSymbolAddress((void**)&pV,     g_V);
    cudaGetSymbolAddress((void**)&pctx,   g_ctx);
    cudaGetSymbolAddress((void**)&pswarm, g_swarm);
    cudaGetSymbolAddress((void**)&pKb,    g_Kb);
    cudaGetSymbolAddress((void**)&pVb,    g_Vb);
    cudaGetSymbolAddress((void**)&pOp,    g_Opart);
    cudaGetSymbolAddress((void**)&plp,    g_lpart);

    k_flag_init<<<1, 1>>>();
    k_flag_detect<<<16, 256>>>(cls);

    // CNN encoder
    k_conv1<<<(NB * H1 * 6) / 256, 256>>>(img, c1w, c1b, pc1);
    k_conv2<<<(NB * H2 * 4) / 256, 256>>>(pc1, c2w, c2b, pflat);   // 1024 blocks, 2px/thread

    // vis_feat = relu(flat @ fc_vis_w^T + b) into g_feat[:, :128]
    { dim3 g(128 / 64, NB / 128); k_gemm128<<<g, 256>>>(pflat, FLAT, fvw, FLAT, fvb, pfeat, FEAT, FLAT, 1); }
    k_embed<<<(NB * 16) / 256, 256>>>(cls, emb, pfeat);

    // GRU
    { dim3 g(G3H / 64, NB / 128); k_gemm128<<<g, 256>>>(pfeat, FEAT, wih, FEAT, bih, pgi, G3H, FEAT, 0); }
    { dim3 g(G3H / 64, NB / 128); k_gemm128<<<g, 256>>>(h0,    HD,   whh, HD,   bhh, pgh, G3H, HD,   0); }
    k_gru<<<(NB * HD) / 256, 256>>>(pgi, pgh, h0, nh);

    // Q, K, V projections (fp32)
    { dim3 g(HD / 64, NB / 128); k_gemm128<<<g, 256>>>(nh, HD, wqw, HD, wqb, pQ, HD, HD, 0); }
    { dim3 g(HD / 64, NB / 128); k_gemm128<<<g, 256>>>(nh, HD, wkw, HD, wkb, pK, HD, HD, 0); }
    { dim3 g(HD / 64, NB / 128); k_gemm128<<<g, 256>>>(nh, HD, wvw, HD, wvb, pV, HD, HD, 0); }

    // bf16 prep
    k_cvtbf<<<(NB * HD / 2) / 256, 256>>>(pK, pKb);
    k_cvtbf<<<(NB * HD / 2) / 256, 256>>>(pV, pVb);

    // mma.sync flash attention
    const int attn_smem = 65536;
    cudaFuncSetAttribute(k_attn_mma, cudaFuncAttributeMaxDynamicSharedMemorySize, attn_smem);
    k_attn_mma<<<128, 256, attn_smem>>>(pQ, pKb, pVb, adj, pOp, plp);
    k_merge<<<(NB * HD) / 256, 256>>>(pOp, plp, pctx);

    // attention output projection
    { dim3 g(HD / 64, NB / 128); k_gemm128<<<g, 256>>>(pctx, HD, aow, HD, aob, pswarm, HD, HD, 0); }

    k_fcq<<<(NB * 5 + 255) / 256, 256>>>(nh, pswarm, fqw, fqb, qout);
}